// round 2
// baseline (speedup 1.0000x reference)
#include <cuda_runtime.h>
#include <math.h>

#define T_LEN 128
#define F_DIM 16
#define MLAN 256

// Operator parameters (lap is block-tridiagonal; fully described by these):
__device__ float g_Mi[256];   // interior diagonal block of lap (16x16), row-major M[f][g]
__device__ float g_Mb[256];   // boundary diagonal block (t=0,127)
__device__ float g_eii[16];   // interior-interior temporal coupling (diag 16-vec)
__device__ float g_ebi[16];   // boundary-interior temporal coupling
__device__ float g_c;         // 2 / sigma_max(lap)

__device__ __forceinline__ float block_reduce_128(float val, volatile float* sred) {
    #pragma unroll
    for (int o = 16; o > 0; o >>= 1) val += __shfl_xor_sync(0xFFFFFFFFu, val, o);
    __syncthreads();   // also fences prior shared reads before sred reuse
    if ((threadIdx.x & 31) == 0) sred[threadIdx.x >> 5] = val;
    __syncthreads();
    return (sred[0] + sred[1]) + (sred[2] + sred[3]);
}

// ---------------------------------------------------------------------------
// Kernel 1: build operator params from adj_param, run Lanczos (m=256) on the
// symmetric PSD operator B = L^T L (L = lap, nonsymmetric), extract
// lambda_max(B) via Sturm bisection, store c = 2/sqrt(lambda_max).
// Single block, 128 threads: thread t owns time step t (16 features in regs).
// ---------------------------------------------------------------------------
__global__ void __launch_bounds__(128) setup_lanczos_kernel(const float* __restrict__ adj) {
    __shared__ float sAhat[16][16];
    __shared__ float sMi[16][17],  sMb[16][17];    // M rows
    __shared__ float sMiT[16][17], sMbT[16][17];   // M^T rows
    __shared__ float seii[16], sebi[16];
    __shared__ float spb[16], spi[16];
    __shared__ float vsh[128][17];
    __shared__ float ush[128][17];
    __shared__ float sred[4];
    __shared__ float salpha[MLAN], sbeta[MLAN];
    __shared__ float slo, shi;
    __shared__ int   sflag[128];

    const int tid = threadIdx.x;

    // ---- build Ahat = sigmoid(adj) off-diagonal + I (row-major [f][g]) ----
    for (int i = tid; i < 256; i += 128) {
        int f = i >> 4, g = i & 15;
        float val = (f == g) ? 1.0f : 1.0f / (1.0f + expf(-adj[i]));
        sAhat[f][g] = val;
    }
    __syncthreads();

    // ---- degrees (ROW sums of adj): d[(t,f)] = rowsum_f + s_t ----
    if (tid < 16) {
        float a = 0.0f;
        #pragma unroll
        for (int g = 0; g < 16; g++) a += sAhat[tid][g];   // includes diag 1
        spb[tid] = rsqrtf(a + 1.0f);   // boundary (one temporal edge)
        spi[tid] = rsqrtf(a + 2.0f);   // interior (two temporal edges)
    }
    __syncthreads();

    // ---- lap diag blocks: M = I - diag(p) Ahat diag(p); edges: -p_t p_{t'} ----
    for (int i = tid; i < 256; i += 128) {
        int f = i >> 4, g = i & 15;
        float diag = (f == g) ? 1.0f : 0.0f;
        float mi = diag - spi[f] * sAhat[f][g] * spi[g];
        float mb = diag - spb[f] * sAhat[f][g] * spb[g];
        sMi[f][g] = mi;   sMb[f][g] = mb;
        sMiT[g][f] = mi;  sMbT[g][f] = mb;
        g_Mi[i] = mi;     g_Mb[i] = mb;
    }
    if (tid < 16) {
        float eii = -spi[tid] * spi[tid];
        float ebi = -spb[tid] * spi[tid];
        seii[tid] = eii;  sebi[tid] = ebi;
        g_eii[tid] = eii; g_ebi[tid] = ebi;
    }
    __syncthreads();

    // ---- Lanczos on B = L^T L (2048-dim). thread t holds v[t][0..15] ----
    const int t = tid;
    const bool bnd = (t == 0 || t == 127);
    float v[16], vp[16], u[16], w[16];
    #pragma unroll
    for (int f = 0; f < 16; f++) {
        unsigned h = (unsigned)(t * 16 + f) * 2654435761u + 0x9E3779B9u;
        h ^= h >> 15; h *= 0x2C1B3C6Du; h ^= h >> 12; h *= 0x297A2D39u; h ^= h >> 15;
        v[f] = (float)(h & 0xFFFFFFu) * (1.0f / 16777216.0f) - 0.5f;
        vp[f] = 0.0f;
    }
    {
        float pa = 0.0f;
        #pragma unroll
        for (int f = 0; f < 16; f++) pa += v[f] * v[f];
        float nn = block_reduce_128(pa, sred);
        float r = rsqrtf(nn);
        #pragma unroll
        for (int f = 0; f < 16; f++) v[f] *= r;
    }

    float bprev = 0.0f;
    for (int j = 0; j < MLAN; j++) {
        // publish v
        #pragma unroll
        for (int f = 0; f < 16; f++) vsh[t][f] = v[f];
        __syncthreads();

        // u = L v  (row action of M)
        #pragma unroll
        for (int f = 0; f < 16; f++) {
            const float* Mr = bnd ? sMb[f] : sMi[f];
            float acc = 0.0f;
            #pragma unroll
            for (int g = 0; g < 16; g++) acc += Mr[g] * v[g];
            u[f] = acc;
        }
        if (t > 0) {
            const float* el = (t == 1 || t == 127) ? sebi : seii;
            #pragma unroll
            for (int f = 0; f < 16; f++) u[f] += el[f] * vsh[t - 1][f];
        }
        if (t < 127) {
            const float* er = (t == 0 || t == 126) ? sebi : seii;
            #pragma unroll
            for (int f = 0; f < 16; f++) u[f] += er[f] * vsh[t + 1][f];
        }

        // publish u
        #pragma unroll
        for (int f = 0; f < 16; f++) ush[t][f] = u[f];
        __syncthreads();

        // w = L^T u  (transposed diag blocks, same edge couplings)
        #pragma unroll
        for (int f = 0; f < 16; f++) {
            const float* Mr = bnd ? sMbT[f] : sMiT[f];
            float acc = 0.0f;
            #pragma unroll
            for (int g = 0; g < 16; g++) acc += Mr[g] * u[g];
            w[f] = acc;
        }
        if (t > 0) {
            const float* el = (t == 1 || t == 127) ? sebi : seii;
            #pragma unroll
            for (int f = 0; f < 16; f++) w[f] += el[f] * ush[t - 1][f];
        }
        if (t < 127) {
            const float* er = (t == 0 || t == 126) ? sebi : seii;
            #pragma unroll
            for (int f = 0; f < 16; f++) w[f] += er[f] * ush[t + 1][f];
        }

        float pa = 0.0f;
        #pragma unroll
        for (int f = 0; f < 16; f++) pa += v[f] * w[f];
        float alpha = block_reduce_128(pa, sred);

        float pb2 = 0.0f;
        #pragma unroll
        for (int f = 0; f < 16; f++) {
            w[f] -= alpha * v[f] + bprev * vp[f];
            pb2 += w[f] * w[f];
        }
        float ss = block_reduce_128(pb2, sred);
        float beta = sqrtf(ss);
        if (tid == 0) { salpha[j] = alpha; sbeta[j] = beta; }
        float rb = (beta > 1e-30f) ? 1.0f / beta : 0.0f;
        #pragma unroll
        for (int f = 0; f < 16; f++) { vp[f] = v[f]; v[f] = w[f] * rb; }
        bprev = beta;
    }
    __syncthreads();

    // ---- largest Ritz value of B via parallel Sturm bisection ----
    if (tid == 0) { slo = 0.0f; shi = 6.01f; }
    __syncthreads();
    for (int r = 0; r < 3; r++) {
        float lo = slo, hi = shi;
        float x = lo + (hi - lo) * (float)(tid + 1) * (1.0f / 129.0f);
        int cnt = 0;
        float d = salpha[0] - x;
        if (d < 0.0f) cnt++;
        for (int i = 1; i < MLAN; i++) {
            float b = sbeta[i - 1];
            float dd = (fabsf(d) < 1e-20f) ? ((d < 0.0f) ? -1e-20f : 1e-20f) : d;
            d = (salpha[i] - x) - (b * b) / dd;
            if (d < 0.0f) cnt++;
        }
        sflag[tid] = (cnt < MLAN) ? 1 : 0;   // 1 => lambda_max >= x
        __syncthreads();
        if (tid == 0) {
            float nlo = lo, nhi = hi;
            for (int i = 0; i < 128; i++) {
                float xi = lo + (hi - lo) * (float)(i + 1) * (1.0f / 129.0f);
                if (sflag[i]) nlo = xi; else { nhi = xi; break; }
            }
            slo = nlo; shi = nhi;
        }
        __syncthreads();
    }
    if (tid == 0) {
        float lmax_B = 0.5f * (slo + shi);
        g_c = 2.0f / sqrtf(lmax_B);       // 2 / sigma_max(L)
    }
}

// ---------------------------------------------------------------------------
// Kernel 2: fused main compute. One block per batch row, thread t = time step.
// Left-multiplication: y1 = L_s^T y0, y2 = 2 L_s^T y1 - y0,
// out = y0 W0 + y1 W1 + y2 W2 + bias.  (L_s = c*lap - I)
// Shared blocks stored TRANSPOSED so the inner loop is a plain row dot.
// ---------------------------------------------------------------------------
__global__ void __launch_bounds__(128) sgconv_main_kernel(
    const float* __restrict__ x, const float* __restrict__ weight,
    const float* __restrict__ bias, float* __restrict__ out) {
    __shared__ float sAiT[16][17], sAbT[16][17];   // (c*M - I)^T rows
    __shared__ float sceii[16], scebi[16];
    __shared__ float sW0[16][16], sW1[16][16], sW2[16][16];
    __shared__ float sbias[16];
    __shared__ float vsh[128][17];

    const int tid = threadIdx.x;
    const float c = g_c;

    for (int i = tid; i < 256; i += 128) {
        int f = i >> 4, g = i & 15;
        float diag = (f == g) ? 1.0f : 0.0f;
        sAiT[g][f] = c * g_Mi[i] - diag;   // transposed store
        sAbT[g][f] = c * g_Mb[i] - diag;
        sW0[f][g] = weight[i];
        sW1[f][g] = weight[256 + i];
        sW2[f][g] = weight[512 + i];
    }
    if (tid < 16) {
        sceii[tid] = c * g_eii[tid];
        scebi[tid] = c * g_ebi[tid];
        sbias[tid] = bias[tid];
    }

    const int t = tid;
    const bool bnd = (t == 0 || t == 127);

    // load x[b, t, :] (64B per thread, coalesced)
    float y0[16];
    const float4* xb = (const float4*)(x + (size_t)blockIdx.x * 2048 + t * 16);
    #pragma unroll
    for (int q = 0; q < 4; q++) {
        float4 vv = xb[q];
        y0[4 * q + 0] = vv.x; y0[4 * q + 1] = vv.y;
        y0[4 * q + 2] = vv.z; y0[4 * q + 3] = vv.w;
    }
    #pragma unroll
    for (int f = 0; f < 16; f++) vsh[t][f] = y0[f];
    __syncthreads();   // covers shared param init + vsh publish

    // y1 = L_s^T y0
    float y1[16];
    #pragma unroll
    for (int f = 0; f < 16; f++) {
        const float* Ar = bnd ? sAbT[f] : sAiT[f];
        float acc = 0.0f;
        #pragma unroll
        for (int g = 0; g < 16; g++) acc += Ar[g] * y0[g];
        y1[f] = acc;
    }
    if (t > 0) {
        const float* el = (t == 1 || t == 127) ? scebi : sceii;
        #pragma unroll
        for (int f = 0; f < 16; f++) y1[f] += el[f] * vsh[t - 1][f];
    }
    if (t < 127) {
        const float* er = (t == 0 || t == 126) ? scebi : sceii;
        #pragma unroll
        for (int f = 0; f < 16; f++) y1[f] += er[f] * vsh[t + 1][f];
    }
    __syncthreads();
    #pragma unroll
    for (int f = 0; f < 16; f++) vsh[t][f] = y1[f];
    __syncthreads();

    // y2 = 2 * L_s^T y1 - y0
    float y2[16];
    #pragma unroll
    for (int f = 0; f < 16; f++) {
        const float* Ar = bnd ? sAbT[f] : sAiT[f];
        float acc = 0.0f;
        #pragma unroll
        for (int g = 0; g < 16; g++) acc += Ar[g] * y1[g];
        y2[f] = acc;
    }
    if (t > 0) {
        const float* el = (t == 1 || t == 127) ? scebi : sceii;
        #pragma unroll
        for (int f = 0; f < 16; f++) y2[f] += el[f] * vsh[t - 1][f];
    }
    if (t < 127) {
        const float* er = (t == 0 || t == 126) ? scebi : sceii;
        #pragma unroll
        for (int f = 0; f < 16; f++) y2[f] += er[f] * vsh[t + 1][f];
    }
    #pragma unroll
    for (int f = 0; f < 16; f++) y2[f] = 2.0f * y2[f] - y0[f];

    // out[t, o] = sum_f y0 W0 + y1 W1 + y2 W2 + bias
    float ov[16];
    #pragma unroll
    for (int o = 0; o < 16; o++) {
        float acc = sbias[o];
        #pragma unroll
        for (int f = 0; f < 16; f++) {
            acc += y0[f] * sW0[f][o];
            acc += y1[f] * sW1[f][o];
            acc += y2[f] * sW2[f][o];
        }
        ov[o] = acc;
    }
    float4* ob = (float4*)(out + (size_t)blockIdx.x * 2048 + t * 16);
    #pragma unroll
    for (int q = 0; q < 4; q++) {
        float4 vv;
        vv.x = ov[4 * q + 0]; vv.y = ov[4 * q + 1];
        vv.z = ov[4 * q + 2]; vv.w = ov[4 * q + 3];
        ob[q] = vv;
    }
}

extern "C" void kernel_launch(void* const* d_in, const int* in_sizes, int n_in,
                              void* d_out, int out_size) {
    const float* x      = (const float*)d_in[0];  // [1024,128,16]
    const float* weight = (const float*)d_in[1];  // [3,16,16]
    const float* bias   = (const float*)d_in[2];  // [16]
    const float* adj    = (const float*)d_in[3];  // [16,16]
    int batch = in_sizes[0] / (T_LEN * F_DIM);

    setup_lanczos_kernel<<<1, 128>>>(adj);
    sgconv_main_kernel<<<batch, 128>>>(x, weight, bias, (float*)d_out);
}

// round 4
// speedup vs baseline: 1.8931x; 1.8931x over previous
#include <cuda_runtime.h>
#include <math.h>

#define T_LEN 128
#define F_DIM 16
#define MLAN 128

// Operator parameters (lap is block-tridiagonal; fully described by these):
__device__ float g_Mi[256];   // interior diagonal block of lap (16x16), row-major M[f][g]
__device__ float g_Mb[256];   // boundary diagonal block (t=0,127)
__device__ float g_eii[16];   // interior-interior temporal coupling (diag 16-vec)
__device__ float g_ebi[16];   // boundary-interior temporal coupling
__device__ float g_c;         // 2 / sigma_max(lap)

// ---------------------------------------------------------------------------
// Kernel 1: build operator params from adj_param, run Lanczos (m=128) on the
// symmetric PSD operator B = L^T L (L = lap, nonsymmetric), extract
// lambda_max(B) via Sturm bisection, store c = 2/sqrt(lambda_max).
// 512 threads: thread (t, q) owns time step t, features 4q..4q+3.
// Warp = 32 consecutive t at fixed q => all M-row reads are broadcasts.
// ---------------------------------------------------------------------------
__global__ void __launch_bounds__(512) setup_lanczos_kernel(const float* __restrict__ adj) {
    __shared__ float sAhat[16][16];
    __shared__ float sMi[16][16],  sMb[16][16];    // M rows (64B-aligned rows)
    __shared__ float sMiT[16][16], sMbT[16][16];   // M^T rows
    __shared__ float seii[16], sebi[16];
    __shared__ float spb[16], spi[16];
    __shared__ float vsh[128][20];                 // pad 20: 16B-aligned rows, conflict-free
    __shared__ float ush[128][20];
    __shared__ float sredA[16], sredB[16];
    __shared__ float salpha[MLAN], sbeta[MLAN];
    __shared__ float slo, shi;
    __shared__ int   sflag[128];

    const int tid  = threadIdx.x;
    const int lane = tid & 31;
    const int wrp  = tid >> 5;

    // ---- build Ahat = sigmoid(adj) off-diagonal + I (row-major [f][g]) ----
    if (tid < 256) {
        int f = tid >> 4, g = tid & 15;
        sAhat[f][g] = (f == g) ? 1.0f : 1.0f / (1.0f + expf(-adj[tid]));
    }
    __syncthreads();

    // ---- degrees (ROW sums): d[(t,f)] = rowsum_f + s_t ----
    if (tid < 16) {
        float a = 0.0f;
        #pragma unroll
        for (int g = 0; g < 16; g++) a += sAhat[tid][g];   // includes diag 1
        spb[tid] = rsqrtf(a + 1.0f);   // boundary (one temporal edge)
        spi[tid] = rsqrtf(a + 2.0f);   // interior (two temporal edges)
    }
    __syncthreads();

    // ---- lap diag blocks: M = I - diag(p) Ahat diag(p); edges: -p_t p_{t'} ----
    if (tid < 256) {
        int f = tid >> 4, g = tid & 15;
        float diag = (f == g) ? 1.0f : 0.0f;
        float mi = diag - spi[f] * sAhat[f][g] * spi[g];
        float mb = diag - spb[f] * sAhat[f][g] * spb[g];
        sMi[f][g] = mi;   sMb[f][g] = mb;
        sMiT[g][f] = mi;  sMbT[g][f] = mb;
        g_Mi[tid] = mi;   g_Mb[tid] = mb;
    }
    if (tid < 16) {
        float eii = -spi[tid] * spi[tid];
        float ebi = -spb[tid] * spi[tid];
        seii[tid] = eii;  sebi[tid] = ebi;
        g_eii[tid] = eii; g_ebi[tid] = ebi;
    }
    __syncthreads();

    // ---- Lanczos on B = L^T L (2048-dim) ----
    const int t  = tid & 127;
    const int q  = tid >> 7;          // feature quad 0..3
    const int fb = q << 2;
    const bool bnd = (t == 0 || t == 127);

    float v4[4], vp4[4], u4[4], w4[4];
    #pragma unroll
    for (int j = 0; j < 4; j++) {
        unsigned h = (unsigned)(t * 16 + fb + j) * 2654435761u + 0x9E3779B9u;
        h ^= h >> 15; h *= 0x2C1B3C6Du; h ^= h >> 12; h *= 0x297A2D39u; h ^= h >> 15;
        v4[j] = (float)(h & 0xFFFFFFu) * (1.0f / 16777216.0f) - 0.5f;
        vp4[j] = 0.0f;
    }

    // block reduce over 512 threads
    auto reduce512 = [&](float val, float* sred) -> float {
        #pragma unroll
        for (int o = 16; o > 0; o >>= 1) val += __shfl_xor_sync(0xFFFFFFFFu, val, o);
        if (lane == 0) sred[wrp] = val;
        __syncthreads();
        float4 r0 = ((float4*)sred)[0], r1 = ((float4*)sred)[1];
        float4 r2 = ((float4*)sred)[2], r3 = ((float4*)sred)[3];
        return ((r0.x + r0.y) + (r0.z + r0.w)) + ((r1.x + r1.y) + (r1.z + r1.w))
             + ((r2.x + r2.y) + (r2.z + r2.w)) + ((r3.x + r3.y) + (r3.z + r3.w));
    };

    {
        float pa = 0.0f;
        #pragma unroll
        for (int j = 0; j < 4; j++) pa += v4[j] * v4[j];
        float nn = reduce512(pa, sredA);
        float r = rsqrtf(nn);
        #pragma unroll
        for (int j = 0; j < 4; j++) v4[j] *= r;
    }

    float bprev = 0.0f;
    for (int it = 0; it < MLAN; it++) {
        // publish v (thread writes its quad)
        ((float4*)&vsh[t][0])[q] = make_float4(v4[0], v4[1], v4[2], v4[3]);
        __syncthreads();

        // u = L v : rows fb..fb+3
        float4 a0 = ((float4*)&vsh[t][0])[0], a1 = ((float4*)&vsh[t][0])[1];
        float4 a2 = ((float4*)&vsh[t][0])[2], a3 = ((float4*)&vsh[t][0])[3];
        #pragma unroll
        for (int j = 0; j < 4; j++) {
            const float4* R = (const float4*)(bnd ? &sMb[fb + j][0] : &sMi[fb + j][0]);
            float4 m0 = R[0], m1 = R[1], m2 = R[2], m3 = R[3];
            u4[j] = (m0.x*a0.x + m0.y*a0.y + m0.z*a0.z + m0.w*a0.w)
                  + (m1.x*a1.x + m1.y*a1.y + m1.z*a1.z + m1.w*a1.w)
                  + (m2.x*a2.x + m2.y*a2.y + m2.z*a2.z + m2.w*a2.w)
                  + (m3.x*a3.x + m3.y*a3.y + m3.z*a3.z + m3.w*a3.w);
        }
        if (t > 0) {
            float4 el = ((const float4*)((t == 1 || t == 127) ? sebi : seii))[q];
            float4 vm = ((float4*)&vsh[t - 1][0])[q];
            u4[0] += el.x * vm.x; u4[1] += el.y * vm.y;
            u4[2] += el.z * vm.z; u4[3] += el.w * vm.w;
        }
        if (t < 127) {
            float4 er = ((const float4*)((t == 0 || t == 126) ? sebi : seii))[q];
            float4 vq = ((float4*)&vsh[t + 1][0])[q];
            u4[0] += er.x * vq.x; u4[1] += er.y * vq.y;
            u4[2] += er.z * vq.z; u4[3] += er.w * vq.w;
        }

        // publish u
        ((float4*)&ush[t][0])[q] = make_float4(u4[0], u4[1], u4[2], u4[3]);
        __syncthreads();

        // w = L^T u
        float4 b0 = ((float4*)&ush[t][0])[0], b1 = ((float4*)&ush[t][0])[1];
        float4 b2 = ((float4*)&ush[t][0])[2], b3 = ((float4*)&ush[t][0])[3];
        #pragma unroll
        for (int j = 0; j < 4; j++) {
            const float4* R = (const float4*)(bnd ? &sMbT[fb + j][0] : &sMiT[fb + j][0]);
            float4 m0 = R[0], m1 = R[1], m2 = R[2], m3 = R[3];
            w4[j] = (m0.x*b0.x + m0.y*b0.y + m0.z*b0.z + m0.w*b0.w)
                  + (m1.x*b1.x + m1.y*b1.y + m1.z*b1.z + m1.w*b1.w)
                  + (m2.x*b2.x + m2.y*b2.y + m2.z*b2.z + m2.w*b2.w)
                  + (m3.x*b3.x + m3.y*b3.y + m3.z*b3.z + m3.w*b3.w);
        }
        if (t > 0) {
            float4 el = ((const float4*)((t == 1 || t == 127) ? sebi : seii))[q];
            float4 um = ((float4*)&ush[t - 1][0])[q];
            w4[0] += el.x * um.x; w4[1] += el.y * um.y;
            w4[2] += el.z * um.z; w4[3] += el.w * um.w;
        }
        if (t < 127) {
            float4 er = ((const float4*)((t == 0 || t == 126) ? sebi : seii))[q];
            float4 uq = ((float4*)&ush[t + 1][0])[q];
            w4[0] += er.x * uq.x; w4[1] += er.y * uq.y;
            w4[2] += er.z * uq.z; w4[3] += er.w * uq.w;
        }

        float pa = (v4[0]*w4[0] + v4[1]*w4[1]) + (v4[2]*w4[2] + v4[3]*w4[3]);
        float alpha = reduce512(pa, sredA);

        float pb = 0.0f;
        #pragma unroll
        for (int j = 0; j < 4; j++) {
            w4[j] -= alpha * v4[j] + bprev * vp4[j];
            pb += w4[j] * w4[j];
        }
        float ss = reduce512(pb, sredB);
        float beta = sqrtf(ss);
        if (tid == 0) { salpha[it] = alpha; sbeta[it] = beta; }
        float rb = (beta > 1e-30f) ? 1.0f / beta : 0.0f;
        #pragma unroll
        for (int j = 0; j < 4; j++) { vp4[j] = v4[j]; v4[j] = w4[j] * rb; }
        bprev = beta;
    }
    __syncthreads();

    // ---- largest Ritz value of B via parallel Sturm bisection ----
    if (tid == 0) { slo = 0.0f; shi = 6.01f; }
    __syncthreads();
    for (int r = 0; r < 3; r++) {
        float lo = slo, hi = shi;
        if (tid < 128) {
            float x = lo + (hi - lo) * (float)(tid + 1) * (1.0f / 129.0f);
            int cnt = 0;
            float d = salpha[0] - x;
            if (d < 0.0f) cnt++;
            for (int i = 1; i < MLAN; i++) {
                float b = sbeta[i - 1];
                float dd = (fabsf(d) < 1e-20f) ? ((d < 0.0f) ? -1e-20f : 1e-20f) : d;
                d = (salpha[i] - x) - (b * b) / dd;
                if (d < 0.0f) cnt++;
            }
            sflag[tid] = (cnt < MLAN) ? 1 : 0;   // 1 => lambda_max >= x
        }
        __syncthreads();
        if (tid == 0) {
            float nlo = lo, nhi = hi;
            for (int i = 0; i < 128; i++) {
                float xi = lo + (hi - lo) * (float)(i + 1) * (1.0f / 129.0f);
                if (sflag[i]) nlo = xi; else { nhi = xi; break; }
            }
            slo = nlo; shi = nhi;
        }
        __syncthreads();
    }
    if (tid == 0) {
        float lmax_B = 0.5f * (slo + shi);
        g_c = 2.0f / sqrtf(lmax_B);       // 2 / sigma_max(L)
    }
}

// ---------------------------------------------------------------------------
// Kernel 2: fused main compute. One block per batch row, thread t = time step.
// Left-multiplication: y1 = L_s^T y0, y2 = 2 L_s^T y1 - y0,
// out = y0 W0 + y1 W1 + y2 W2 + bias.  (L_s = c*lap - I)
// Blocks stored TRANSPOSED; all matrix/weight reads are float4 broadcasts.
// ---------------------------------------------------------------------------
__global__ void __launch_bounds__(128) sgconv_main_kernel(
    const float* __restrict__ x, const float* __restrict__ weight,
    const float* __restrict__ bias, float* __restrict__ out) {
    __shared__ float sAiT[16][16], sAbT[16][16];   // (c*M - I)^T rows, 64B-aligned
    __shared__ float scei[16], sceb[16];
    __shared__ float sW0[16][16], sW1[16][16], sW2[16][16];
    __shared__ float sbias[16];
    __shared__ float vsh[128][20];

    const int tid = threadIdx.x;
    const float c = g_c;

    #pragma unroll
    for (int r = 0; r < 2; r++) {
        int i = tid + r * 128;
        int f = i >> 4, g = i & 15;
        float diag = (f == g) ? 1.0f : 0.0f;
        sAiT[g][f] = c * g_Mi[i] - diag;   // transposed store
        sAbT[g][f] = c * g_Mb[i] - diag;
        sW0[f][g] = weight[i];
        sW1[f][g] = weight[256 + i];
        sW2[f][g] = weight[512 + i];
    }
    if (tid < 16) {
        scei[tid] = c * g_eii[tid];
        sceb[tid] = c * g_ebi[tid];
        sbias[tid] = bias[tid];
    }

    const int t = tid;
    const bool bnd = (t == 0 || t == 127);

    // load x[b, t, :] (64B per thread, coalesced)
    float y0[16];
    const float4* xb = (const float4*)(x + (size_t)blockIdx.x * 2048 + t * 16);
    #pragma unroll
    for (int qq = 0; qq < 4; qq++) {
        float4 vv = xb[qq];
        y0[4*qq+0] = vv.x; y0[4*qq+1] = vv.y; y0[4*qq+2] = vv.z; y0[4*qq+3] = vv.w;
        ((float4*)&vsh[t][0])[qq] = vv;
    }
    __syncthreads();   // covers shared param init + vsh publish

    // structured apply: dst = Ls^T src + edge terms. src in regs, neighbors in vsh.
    auto apply_ls = [&](float* DST, const float* SRC) {
        float nb[16];
        #pragma unroll
        for (int f = 0; f < 16; f++) nb[f] = 0.0f;
        if (t > 0) {
            const float* el = (t == 1 || t == 127) ? sceb : scei;
            #pragma unroll
            for (int qq = 0; qq < 4; qq++) {
                float4 e4 = ((const float4*)el)[qq];
                float4 m4 = ((float4*)&vsh[t - 1][0])[qq];
                nb[4*qq+0] += e4.x * m4.x; nb[4*qq+1] += e4.y * m4.y;
                nb[4*qq+2] += e4.z * m4.z; nb[4*qq+3] += e4.w * m4.w;
            }
        }
        if (t < 127) {
            const float* er = (t == 0 || t == 126) ? sceb : scei;
            #pragma unroll
            for (int qq = 0; qq < 4; qq++) {
                float4 e4 = ((const float4*)er)[qq];
                float4 p4 = ((float4*)&vsh[t + 1][0])[qq];
                nb[4*qq+0] += e4.x * p4.x; nb[4*qq+1] += e4.y * p4.y;
                nb[4*qq+2] += e4.z * p4.z; nb[4*qq+3] += e4.w * p4.w;
            }
        }
        #pragma unroll
        for (int f = 0; f < 16; f++) {
            const float4* R = (const float4*)(bnd ? &sAbT[f][0] : &sAiT[f][0]);
            float4 m0 = R[0], m1 = R[1], m2 = R[2], m3 = R[3];
            DST[f] = nb[f]
                + (m0.x*SRC[0]  + m0.y*SRC[1]  + m0.z*SRC[2]  + m0.w*SRC[3])
                + (m1.x*SRC[4]  + m1.y*SRC[5]  + m1.z*SRC[6]  + m1.w*SRC[7])
                + (m2.x*SRC[8]  + m2.y*SRC[9]  + m2.z*SRC[10] + m2.w*SRC[11])
                + (m3.x*SRC[12] + m3.y*SRC[13] + m3.z*SRC[14] + m3.w*SRC[15]);
        }
    };

    // y1 = L_s^T y0
    float y1[16];
    apply_ls(y1, y0);
    __syncthreads();
    #pragma unroll
    for (int qq = 0; qq < 4; qq++)
        ((float4*)&vsh[t][0])[qq] = make_float4(y1[4*qq], y1[4*qq+1], y1[4*qq+2], y1[4*qq+3]);
    __syncthreads();

    // y2 = 2 * L_s^T y1 - y0
    float y2[16];
    apply_ls(y2, y1);
    #pragma unroll
    for (int f = 0; f < 16; f++) y2[f] = 2.0f * y2[f] - y0[f];

    // out[t, o] = sum_f y0 W0 + y1 W1 + y2 W2 + bias  (f-outer, o-inner)
    float ov[16];
    #pragma unroll
    for (int qq = 0; qq < 4; qq++) {
        float4 b4 = ((const float4*)sbias)[qq];
        ov[4*qq+0] = b4.x; ov[4*qq+1] = b4.y; ov[4*qq+2] = b4.z; ov[4*qq+3] = b4.w;
    }
    #pragma unroll
    for (int f = 0; f < 16; f++) {
        float a0 = y0[f], a1 = y1[f], a2 = y2[f];
        const float4* W0r = (const float4*)&sW0[f][0];
        const float4* W1r = (const float4*)&sW1[f][0];
        const float4* W2r = (const float4*)&sW2[f][0];
        #pragma unroll
        for (int qq = 0; qq < 4; qq++) {
            float4 w0 = W0r[qq], w1 = W1r[qq], w2 = W2r[qq];
            ov[4*qq+0] += a0*w0.x + a1*w1.x + a2*w2.x;
            ov[4*qq+1] += a0*w0.y + a1*w1.y + a2*w2.y;
            ov[4*qq+2] += a0*w0.z + a1*w1.z + a2*w2.z;
            ov[4*qq+3] += a0*w0.w + a1*w1.w + a2*w2.w;
        }
    }
    float4* ob = (float4*)(out + (size_t)blockIdx.x * 2048 + t * 16);
    #pragma unroll
    for (int qq = 0; qq < 4; qq++)
        ob[qq] = make_float4(ov[4*qq], ov[4*qq+1], ov[4*qq+2], ov[4*qq+3]);
}

extern "C" void kernel_launch(void* const* d_in, const int* in_sizes, int n_in,
                              void* d_out, int out_size) {
    const float* x      = (const float*)d_in[0];  // [1024,128,16]
    const float* weight = (const float*)d_in[1];  // [3,16,16]
    const float* bias   = (const float*)d_in[2];  // [16]
    const float* adj    = (const float*)d_in[3];  // [16,16]
    int batch = in_sizes[0] / (T_LEN * F_DIM);

    setup_lanczos_kernel<<<1, 512>>>(adj);
    sgconv_main_kernel<<<batch, 128>>>(x, weight, bias, (float*)d_out);
}

// round 5
// speedup vs baseline: 2.2790x; 1.2039x over previous
#include <cuda_runtime.h>
#include <math.h>

#define T_LEN 128
#define F_DIM 16
#define MLAN 96

// Operator parameters (lap is block-tridiagonal; fully described by these):
__device__ float g_Mi[256];   // interior diagonal block of lap (16x16), row-major M[f][g]
__device__ float g_Mb[256];   // boundary diagonal block (t=0,127)
__device__ float g_eii[16];   // interior-interior temporal coupling (diag 16-vec)
__device__ float g_ebi[16];   // boundary-interior temporal coupling
__device__ float g_c;         // 2 / sigma_max(lap)

// ---------------------------------------------------------------------------
// Kernel 1: build operator params from adj_param, run Lanczos (m=96) on the
// symmetric PSD operator B = L^T L (L = lap, nonsymmetric), extract
// lambda_max(B) via Sturm bisection, store c = 2/sqrt(lambda_max).
// 512 threads: thread (t, q) owns time step t, features 4q..4q+3.
// M rows register-cached (loop-invariant); one fused triple-reduction/iter.
// ---------------------------------------------------------------------------
__global__ void __launch_bounds__(512) setup_lanczos_kernel(const float* __restrict__ adj) {
    __shared__ float sAhat[16][16];
    __shared__ float sMi[16][16],  sMb[16][16];    // M rows
    __shared__ float sMiT[16][16], sMbT[16][16];   // M^T rows
    __shared__ float seii[16], sebi[16];
    __shared__ float spb[16], spi[16];
    __shared__ float vsh[128][20];                 // pad 20: 16B-aligned rows
    __shared__ float ush[128][20];
    __shared__ float sredA[16], sredB[16], sredC[16];
    __shared__ float salpha[MLAN], sbeta[MLAN];
    __shared__ float slo, shi;
    __shared__ int   sflag[128];

    const int tid  = threadIdx.x;
    const int lane = tid & 31;
    const int wrp  = tid >> 5;

    // ---- build Ahat = sigmoid(adj) off-diagonal + I (row-major [f][g]) ----
    if (tid < 256) {
        int f = tid >> 4, g = tid & 15;
        sAhat[f][g] = (f == g) ? 1.0f : 1.0f / (1.0f + expf(-adj[tid]));
    }
    __syncthreads();

    // ---- degrees (ROW sums): d[(t,f)] = rowsum_f + s_t ----
    if (tid < 16) {
        float a = 0.0f;
        #pragma unroll
        for (int g = 0; g < 16; g++) a += sAhat[tid][g];   // includes diag 1
        spb[tid] = rsqrtf(a + 1.0f);   // boundary (one temporal edge)
        spi[tid] = rsqrtf(a + 2.0f);   // interior (two temporal edges)
    }
    __syncthreads();

    // ---- lap diag blocks: M = I - diag(p) Ahat diag(p); edges: -p_t p_{t'} ----
    if (tid < 256) {
        int f = tid >> 4, g = tid & 15;
        float diag = (f == g) ? 1.0f : 0.0f;
        float mi = diag - spi[f] * sAhat[f][g] * spi[g];
        float mb = diag - spb[f] * sAhat[f][g] * spb[g];
        sMi[f][g] = mi;   sMb[f][g] = mb;
        sMiT[g][f] = mi;  sMbT[g][f] = mb;
        g_Mi[tid] = mi;   g_Mb[tid] = mb;
    }
    if (tid < 16) {
        float eii = -spi[tid] * spi[tid];
        float ebi = -spb[tid] * spi[tid];
        seii[tid] = eii;  sebi[tid] = ebi;
        g_eii[tid] = eii; g_ebi[tid] = ebi;
    }
    __syncthreads();

    // ---- Lanczos on B = L^T L (2048-dim) ----
    const int t  = tid & 127;
    const int q  = tid >> 7;          // feature quad 0..3
    const int fb = q << 2;
    const bool bnd = (t == 0 || t == 127);

    // register-cache this thread's 4 M rows (loop-invariant)
    float4 Rm[4][4];
    #pragma unroll
    for (int j = 0; j < 4; j++) {
        const float4* R = (const float4*)(bnd ? &sMb[fb + j][0] : &sMi[fb + j][0]);
        Rm[j][0] = R[0]; Rm[j][1] = R[1]; Rm[j][2] = R[2]; Rm[j][3] = R[3];
    }
    // edge coefficient quads (loop-invariant per thread)
    float4 elq = make_float4(0,0,0,0), erq = make_float4(0,0,0,0);
    if (t > 0)   elq = ((const float4*)((t == 1 || t == 127) ? sebi : seii))[q];
    if (t < 127) erq = ((const float4*)((t == 0 || t == 126) ? sebi : seii))[q];

    float v4[4], vp4[4], u4[4], w4[4];
    #pragma unroll
    for (int j = 0; j < 4; j++) {
        unsigned h = (unsigned)(t * 16 + fb + j) * 2654435761u + 0x9E3779B9u;
        h ^= h >> 15; h *= 0x2C1B3C6Du; h ^= h >> 12; h *= 0x297A2D39u; h ^= h >> 15;
        v4[j] = (float)(h & 0xFFFFFFu) * (1.0f / 16777216.0f) - 0.5f;
        vp4[j] = 0.0f;
    }

    auto sum16 = [](float* sred) -> float {
        float4 r0 = ((float4*)sred)[0], r1 = ((float4*)sred)[1];
        float4 r2 = ((float4*)sred)[2], r3 = ((float4*)sred)[3];
        return ((r0.x + r0.y) + (r0.z + r0.w)) + ((r1.x + r1.y) + (r1.z + r1.w))
             + ((r2.x + r2.y) + (r2.z + r2.w)) + ((r3.x + r3.y) + (r3.z + r3.w));
    };

    {   // normalize initial v
        float pa = 0.0f;
        #pragma unroll
        for (int j = 0; j < 4; j++) pa += v4[j] * v4[j];
        #pragma unroll
        for (int o = 16; o > 0; o >>= 1) pa += __shfl_xor_sync(0xFFFFFFFFu, pa, o);
        if (lane == 0) sredA[wrp] = pa;
        __syncthreads();
        float r = rsqrtf(sum16(sredA));
        #pragma unroll
        for (int j = 0; j < 4; j++) v4[j] *= r;
        __syncthreads();
    }

    float bprev = 0.0f;
    for (int it = 0; it < MLAN; it++) {
        // publish v (thread writes its quad)
        ((float4*)&vsh[t][0])[q] = make_float4(v4[0], v4[1], v4[2], v4[3]);
        __syncthreads();

        // u = L v : rows fb..fb+3 from register-cached Rm
        float4 a0 = ((float4*)&vsh[t][0])[0], a1 = ((float4*)&vsh[t][0])[1];
        float4 a2 = ((float4*)&vsh[t][0])[2], a3 = ((float4*)&vsh[t][0])[3];
        #pragma unroll
        for (int j = 0; j < 4; j++) {
            float4 m0 = Rm[j][0], m1 = Rm[j][1], m2 = Rm[j][2], m3 = Rm[j][3];
            u4[j] = (m0.x*a0.x + m0.y*a0.y + m0.z*a0.z + m0.w*a0.w)
                  + (m1.x*a1.x + m1.y*a1.y + m1.z*a1.z + m1.w*a1.w)
                  + (m2.x*a2.x + m2.y*a2.y + m2.z*a2.z + m2.w*a2.w)
                  + (m3.x*a3.x + m3.y*a3.y + m3.z*a3.z + m3.w*a3.w);
        }
        if (t > 0) {
            float4 vm = ((float4*)&vsh[t - 1][0])[q];
            u4[0] += elq.x * vm.x; u4[1] += elq.y * vm.y;
            u4[2] += elq.z * vm.z; u4[3] += elq.w * vm.w;
        }
        if (t < 127) {
            float4 vq = ((float4*)&vsh[t + 1][0])[q];
            u4[0] += erq.x * vq.x; u4[1] += erq.y * vq.y;
            u4[2] += erq.z * vq.z; u4[3] += erq.w * vq.w;
        }

        // publish u
        ((float4*)&ush[t][0])[q] = make_float4(u4[0], u4[1], u4[2], u4[3]);
        __syncthreads();

        // w = L^T u (transposed blocks from shared)
        float4 b0 = ((float4*)&ush[t][0])[0], b1 = ((float4*)&ush[t][0])[1];
        float4 b2 = ((float4*)&ush[t][0])[2], b3 = ((float4*)&ush[t][0])[3];
        #pragma unroll
        for (int j = 0; j < 4; j++) {
            const float4* R = (const float4*)(bnd ? &sMbT[fb + j][0] : &sMiT[fb + j][0]);
            float4 m0 = R[0], m1 = R[1], m2 = R[2], m3 = R[3];
            w4[j] = (m0.x*b0.x + m0.y*b0.y + m0.z*b0.z + m0.w*b0.w)
                  + (m1.x*b1.x + m1.y*b1.y + m1.z*b1.z + m1.w*b1.w)
                  + (m2.x*b2.x + m2.y*b2.y + m2.z*b2.z + m2.w*b2.w)
                  + (m3.x*b3.x + m3.y*b3.y + m3.z*b3.z + m3.w*b3.w);
        }
        if (t > 0) {
            float4 um = ((float4*)&ush[t - 1][0])[q];
            w4[0] += elq.x * um.x; w4[1] += elq.y * um.y;
            w4[2] += elq.z * um.z; w4[3] += elq.w * um.w;
        }
        if (t < 127) {
            float4 uq = ((float4*)&ush[t + 1][0])[q];
            w4[0] += erq.x * uq.x; w4[1] += erq.y * uq.y;
            w4[2] += erq.z * uq.z; w4[3] += erq.w * uq.w;
        }

        // fused triple reduction: alpha = v.w, r = vp.w, s = w.w
        float pa = (v4[0]*w4[0]  + v4[1]*w4[1])  + (v4[2]*w4[2]  + v4[3]*w4[3]);
        float pr = (vp4[0]*w4[0] + vp4[1]*w4[1]) + (vp4[2]*w4[2] + vp4[3]*w4[3]);
        float ps = (w4[0]*w4[0]  + w4[1]*w4[1])  + (w4[2]*w4[2]  + w4[3]*w4[3]);
        #pragma unroll
        for (int o = 16; o > 0; o >>= 1) {
            pa += __shfl_xor_sync(0xFFFFFFFFu, pa, o);
            pr += __shfl_xor_sync(0xFFFFFFFFu, pr, o);
            ps += __shfl_xor_sync(0xFFFFFFFFu, ps, o);
        }
        if (lane == 0) { sredA[wrp] = pa; sredB[wrp] = pr; sredC[wrp] = ps; }
        __syncthreads();
        float alpha = sum16(sredA);
        float rr    = sum16(sredB);
        float ss    = sum16(sredC);
        // ||w - alpha v - bprev vp||^2 = s - 2a^2 - 2b r + a^2 + b^2 (orthonormal v, vp)
        float qn = ss - alpha*alpha - 2.0f*bprev*rr + bprev*bprev;
        qn = fmaxf(qn, 0.0f);
        float beta = sqrtf(qn);
        if (tid == 0) { salpha[it] = alpha; sbeta[it] = beta; }
        float rb = (beta > 1e-30f) ? 1.0f / beta : 0.0f;
        #pragma unroll
        for (int j = 0; j < 4; j++) {
            float wn = w4[j] - alpha * v4[j] - bprev * vp4[j];
            vp4[j] = v4[j]; v4[j] = wn * rb;
        }
        bprev = beta;
    }
    __syncthreads();

    // ---- largest Ritz value of B via parallel Sturm bisection ----
    if (tid == 0) { slo = 0.0f; shi = 6.01f; }
    __syncthreads();
    for (int r = 0; r < 3; r++) {
        float lo = slo, hi = shi;
        if (tid < 128) {
            float x = lo + (hi - lo) * (float)(tid + 1) * (1.0f / 129.0f);
            int cnt = 0;
            float d = salpha[0] - x;
            if (d < 0.0f) cnt++;
            for (int i = 1; i < MLAN; i++) {
                float b = sbeta[i - 1];
                float dd = (fabsf(d) < 1e-20f) ? ((d < 0.0f) ? -1e-20f : 1e-20f) : d;
                d = (salpha[i] - x) - (b * b) / dd;
                if (d < 0.0f) cnt++;
            }
            sflag[tid] = (cnt < MLAN) ? 1 : 0;   // 1 => lambda_max >= x
        }
        __syncthreads();
        if (tid == 0) {
            float nlo = lo, nhi = hi;
            for (int i = 0; i < 128; i++) {
                float xi = lo + (hi - lo) * (float)(i + 1) * (1.0f / 129.0f);
                if (sflag[i]) nlo = xi; else { nhi = xi; break; }
            }
            slo = nlo; shi = nhi;
        }
        __syncthreads();
    }
    if (tid == 0) {
        float lmax_B = 0.5f * (slo + shi);
        g_c = 2.0f / sqrtf(lmax_B);       // 2 / sigma_max(L)
    }
}

// ---------------------------------------------------------------------------
// Kernel 2: fused main compute, SINGLE __syncthreads.
// One block per batch row, thread t = time step. Thread t redundantly computes
// y1 at t-1, t, t+1 from the shared x tile, so y2 (and output) need no second
// barrier. out = y0 W0 + y1 W1 + y2 W2 + bias, L_s = c*lap - I, left-applied.
// ---------------------------------------------------------------------------
__global__ void __launch_bounds__(128) sgconv_main_kernel(
    const float* __restrict__ x, const float* __restrict__ weight,
    const float* __restrict__ bias, float* __restrict__ out) {
    __shared__ float sAiT[16][16], sAbT[16][16];   // (c*M - I)^T rows
    __shared__ float scei[16], sceb[16];
    __shared__ float sW0[16][16], sW1[16][16], sW2[16][16];
    __shared__ float sbias[16];
    __shared__ float vsh[128][20];

    const int tid = threadIdx.x;
    const float c = g_c;

    #pragma unroll
    for (int r = 0; r < 2; r++) {
        int i = tid + r * 128;
        int f = i >> 4, g = i & 15;
        float diag = (f == g) ? 1.0f : 0.0f;
        sAiT[g][f] = c * g_Mi[i] - diag;   // transposed store
        sAbT[g][f] = c * g_Mb[i] - diag;
        sW0[f][g] = weight[i];
        sW1[f][g] = weight[256 + i];
        sW2[f][g] = weight[512 + i];
    }
    if (tid < 16) {
        scei[tid] = c * g_eii[tid];
        sceb[tid] = c * g_ebi[tid];
        sbias[tid] = bias[tid];
    }

    const int t = tid;

    // load x[b, t, :] (64B per thread, coalesced), publish to vsh
    float y0[16];
    const float4* xb = (const float4*)(x + (size_t)blockIdx.x * 2048 + t * 16);
    #pragma unroll
    for (int qq = 0; qq < 4; qq++) {
        float4 vv = xb[qq];
        y0[4*qq+0] = vv.x; y0[4*qq+1] = vv.y; y0[4*qq+2] = vv.z; y0[4*qq+3] = vv.w;
        ((float4*)&vsh[t][0])[qq] = vv;
    }
    __syncthreads();   // the only barrier: params + x tile visible

    // apply L_s^T at arbitrary time tt, src = vsh (x tile)
    auto apply_at = [&](int tt, float* DST) {
        bool b = (tt == 0 || tt == 127);
        float nb[16];
        #pragma unroll
        for (int f = 0; f < 16; f++) nb[f] = 0.0f;
        if (tt > 0) {
            const float* el = (tt == 1 || tt == 127) ? sceb : scei;
            #pragma unroll
            for (int qq = 0; qq < 4; qq++) {
                float4 e4 = ((const float4*)el)[qq];
                float4 m4 = ((float4*)&vsh[tt - 1][0])[qq];
                nb[4*qq+0] += e4.x * m4.x; nb[4*qq+1] += e4.y * m4.y;
                nb[4*qq+2] += e4.z * m4.z; nb[4*qq+3] += e4.w * m4.w;
            }
        }
        if (tt < 127) {
            const float* er = (tt == 0 || tt == 126) ? sceb : scei;
            #pragma unroll
            for (int qq = 0; qq < 4; qq++) {
                float4 e4 = ((const float4*)er)[qq];
                float4 p4 = ((float4*)&vsh[tt + 1][0])[qq];
                nb[4*qq+0] += e4.x * p4.x; nb[4*qq+1] += e4.y * p4.y;
                nb[4*qq+2] += e4.z * p4.z; nb[4*qq+3] += e4.w * p4.w;
            }
        }
        float4 s0 = ((float4*)&vsh[tt][0])[0], s1 = ((float4*)&vsh[tt][0])[1];
        float4 s2 = ((float4*)&vsh[tt][0])[2], s3 = ((float4*)&vsh[tt][0])[3];
        #pragma unroll
        for (int f = 0; f < 16; f++) {
            const float4* R = (const float4*)(b ? &sAbT[f][0] : &sAiT[f][0]);
            float4 m0 = R[0], m1 = R[1], m2 = R[2], m3 = R[3];
            DST[f] = nb[f]
                + (m0.x*s0.x + m0.y*s0.y + m0.z*s0.z + m0.w*s0.w)
                + (m1.x*s1.x + m1.y*s1.y + m1.z*s1.z + m1.w*s1.w)
                + (m2.x*s2.x + m2.y*s2.y + m2.z*s2.z + m2.w*s2.w)
                + (m3.x*s3.x + m3.y*s3.y + m3.z*s3.z + m3.w*s3.w);
        }
    };

    // y1 at t-1, t, t+1 (redundant compute; no second barrier needed)
    float y1m[16], y1c[16], y1p[16];
    apply_at(t, y1c);
    if (t > 0)   apply_at(t - 1, y1m);
    if (t < 127) apply_at(t + 1, y1p);

    // y2 = 2 * L_s^T y1 - y0 (neighbors of y1 held locally)
    float y2[16];
    {
        const bool b = (t == 0 || t == 127);
        float nb[16];
        #pragma unroll
        for (int f = 0; f < 16; f++) nb[f] = 0.0f;
        if (t > 0) {
            const float* el = (t == 1 || t == 127) ? sceb : scei;
            #pragma unroll
            for (int f = 0; f < 16; f++) nb[f] += el[f] * y1m[f];
        }
        if (t < 127) {
            const float* er = (t == 0 || t == 126) ? sceb : scei;
            #pragma unroll
            for (int f = 0; f < 16; f++) nb[f] += er[f] * y1p[f];
        }
        #pragma unroll
        for (int f = 0; f < 16; f++) {
            const float4* R = (const float4*)(b ? &sAbT[f][0] : &sAiT[f][0]);
            float4 m0 = R[0], m1 = R[1], m2 = R[2], m3 = R[3];
            float acc = nb[f]
                + (m0.x*y1c[0]  + m0.y*y1c[1]  + m0.z*y1c[2]  + m0.w*y1c[3])
                + (m1.x*y1c[4]  + m1.y*y1c[5]  + m1.z*y1c[6]  + m1.w*y1c[7])
                + (m2.x*y1c[8]  + m2.y*y1c[9]  + m2.z*y1c[10] + m2.w*y1c[11])
                + (m3.x*y1c[12] + m3.y*y1c[13] + m3.z*y1c[14] + m3.w*y1c[15]);
            y2[f] = 2.0f * acc - y0[f];
        }
    }

    // out[t, o] = sum_f y0 W0 + y1 W1 + y2 W2 + bias  (f-outer, o-inner)
    float ov[16];
    #pragma unroll
    for (int qq = 0; qq < 4; qq++) {
        float4 b4 = ((const float4*)sbias)[qq];
        ov[4*qq+0] = b4.x; ov[4*qq+1] = b4.y; ov[4*qq+2] = b4.z; ov[4*qq+3] = b4.w;
    }
    #pragma unroll
    for (int f = 0; f < 16; f++) {
        float a0 = y0[f], a1 = y1c[f], a2 = y2[f];
        const float4* W0r = (const float4*)&sW0[f][0];
        const float4* W1r = (const float4*)&sW1[f][0];
        const float4* W2r = (const float4*)&sW2[f][0];
        #pragma unroll
        for (int qq = 0; qq < 4; qq++) {
            float4 w0 = W0r[qq], w1 = W1r[qq], w2 = W2r[qq];
            ov[4*qq+0] += a0*w0.x + a1*w1.x + a2*w2.x;
            ov[4*qq+1] += a0*w0.y + a1*w1.y + a2*w2.y;
            ov[4*qq+2] += a0*w0.z + a1*w1.z + a2*w2.z;
            ov[4*qq+3] += a0*w0.w + a1*w1.w + a2*w2.w;
        }
    }
    float4* ob = (float4*)(out + (size_t)blockIdx.x * 2048 + t * 16);
    #pragma unroll
    for (int qq = 0; qq < 4; qq++)
        ob[qq] = make_float4(ov[4*qq], ov[4*qq+1], ov[4*qq+2], ov[4*qq+3]);
}

extern "C" void kernel_launch(void* const* d_in, const int* in_sizes, int n_in,
                              void* d_out, int out_size) {
    const float* x      = (const float*)d_in[0];  // [1024,128,16]
    const float* weight = (const float*)d_in[1];  // [3,16,16]
    const float* bias   = (const float*)d_in[2];  // [16]
    const float* adj    = (const float*)d_in[3];  // [16,16]
    int batch = in_sizes[0] / (T_LEN * F_DIM);

    setup_lanczos_kernel<<<1, 512>>>(adj);
    sgconv_main_kernel<<<batch, 128>>>(x, weight, bias, (float*)d_out);
}

// round 6
// speedup vs baseline: 4.0026x; 1.7563x over previous
#include <cuda_runtime.h>
#include <math.h>

#define T_LEN 128
#define F_DIM 16
#define MLAN 64

// Operator parameters (lap is block-tridiagonal; fully described by these):
__device__ float g_Mi[256];   // interior diagonal block of lap (16x16), row-major M[f][g]
__device__ float g_Mb[256];   // boundary diagonal block (t=0,127)
__device__ float g_eii[16];   // interior-interior temporal coupling (diag 16-vec)
__device__ float g_ebi[16];   // boundary-interior temporal coupling
__device__ float g_c;         // 2 / sigma_max(lap)

// ---------------------------------------------------------------------------
// Kernel 1: build operator params from adj_param, run Lanczos (m=64) on the
// symmetric PSD operator B = L^T L (L = lap, nonsymmetric), extract
// lambda_max(B) via Sturm bisection, store c = 2/sqrt(lambda_max).
// 512 threads: thread (t, q) owns time step t, features 4q..4q+3.
// M rows register-cached (loop-invariant); one fused triple-reduction/iter.
// ---------------------------------------------------------------------------
__global__ void __launch_bounds__(512) setup_lanczos_kernel(const float* __restrict__ adj) {
    __shared__ float sAhat[16][16];
    __shared__ float sMi[16][16],  sMb[16][16];    // M rows
    __shared__ float sMiT[16][16], sMbT[16][16];   // M^T rows
    __shared__ float seii[16], sebi[16];
    __shared__ float spb[16], spi[16];
    __shared__ float vsh[128][20];                 // pad 20: 16B-aligned rows
    __shared__ float ush[128][20];
    __shared__ float sredA[16], sredB[16], sredC[16];
    __shared__ float salpha[MLAN], sbeta[MLAN];
    __shared__ float slo, shi;
    __shared__ int   sflag[128];

    const int tid  = threadIdx.x;
    const int lane = tid & 31;
    const int wrp  = tid >> 5;

    // ---- build Ahat = sigmoid(adj) off-diagonal + I (row-major [f][g]) ----
    if (tid < 256) {
        int f = tid >> 4, g = tid & 15;
        sAhat[f][g] = (f == g) ? 1.0f : 1.0f / (1.0f + expf(-adj[tid]));
    }
    __syncthreads();

    // ---- degrees (ROW sums): d[(t,f)] = rowsum_f + s_t ----
    if (tid < 16) {
        float a = 0.0f;
        #pragma unroll
        for (int g = 0; g < 16; g++) a += sAhat[tid][g];   // includes diag 1
        spb[tid] = rsqrtf(a + 1.0f);   // boundary (one temporal edge)
        spi[tid] = rsqrtf(a + 2.0f);   // interior (two temporal edges)
    }
    __syncthreads();

    // ---- lap diag blocks: M = I - diag(p) Ahat diag(p); edges: -p_t p_{t'} ----
    if (tid < 256) {
        int f = tid >> 4, g = tid & 15;
        float diag = (f == g) ? 1.0f : 0.0f;
        float mi = diag - spi[f] * sAhat[f][g] * spi[g];
        float mb = diag - spb[f] * sAhat[f][g] * spb[g];
        sMi[f][g] = mi;   sMb[f][g] = mb;
        sMiT[g][f] = mi;  sMbT[g][f] = mb;
        g_Mi[tid] = mi;   g_Mb[tid] = mb;
    }
    if (tid < 16) {
        float eii = -spi[tid] * spi[tid];
        float ebi = -spb[tid] * spi[tid];
        seii[tid] = eii;  sebi[tid] = ebi;
        g_eii[tid] = eii; g_ebi[tid] = ebi;
    }
    __syncthreads();

    // ---- Lanczos on B = L^T L (2048-dim) ----
    const int t  = tid & 127;
    const int q  = tid >> 7;          // feature quad 0..3
    const int fb = q << 2;
    const bool bnd = (t == 0 || t == 127);

    // register-cache this thread's 4 M rows (loop-invariant)
    float4 Rm[4][4];
    #pragma unroll
    for (int j = 0; j < 4; j++) {
        const float4* R = (const float4*)(bnd ? &sMb[fb + j][0] : &sMi[fb + j][0]);
        Rm[j][0] = R[0]; Rm[j][1] = R[1]; Rm[j][2] = R[2]; Rm[j][3] = R[3];
    }
    // edge coefficient quads (loop-invariant per thread)
    float4 elq = make_float4(0,0,0,0), erq = make_float4(0,0,0,0);
    if (t > 0)   elq = ((const float4*)((t == 1 || t == 127) ? sebi : seii))[q];
    if (t < 127) erq = ((const float4*)((t == 0 || t == 126) ? sebi : seii))[q];

    float v4[4], vp4[4], u4[4], w4[4];
    #pragma unroll
    for (int j = 0; j < 4; j++) {
        unsigned h = (unsigned)(t * 16 + fb + j) * 2654435761u + 0x9E3779B9u;
        h ^= h >> 15; h *= 0x2C1B3C6Du; h ^= h >> 12; h *= 0x297A2D39u; h ^= h >> 15;
        v4[j] = (float)(h & 0xFFFFFFu) * (1.0f / 16777216.0f) - 0.5f;
        vp4[j] = 0.0f;
    }

    auto sum16 = [](float* sred) -> float {
        float4 r0 = ((float4*)sred)[0], r1 = ((float4*)sred)[1];
        float4 r2 = ((float4*)sred)[2], r3 = ((float4*)sred)[3];
        return ((r0.x + r0.y) + (r0.z + r0.w)) + ((r1.x + r1.y) + (r1.z + r1.w))
             + ((r2.x + r2.y) + (r2.z + r2.w)) + ((r3.x + r3.y) + (r3.z + r3.w));
    };

    {   // normalize initial v
        float pa = 0.0f;
        #pragma unroll
        for (int j = 0; j < 4; j++) pa += v4[j] * v4[j];
        #pragma unroll
        for (int o = 16; o > 0; o >>= 1) pa += __shfl_xor_sync(0xFFFFFFFFu, pa, o);
        if (lane == 0) sredA[wrp] = pa;
        __syncthreads();
        float r = rsqrtf(sum16(sredA));
        #pragma unroll
        for (int j = 0; j < 4; j++) v4[j] *= r;
        __syncthreads();
    }

    float bprev = 0.0f;
    for (int it = 0; it < MLAN; it++) {
        // publish v (thread writes its quad)
        ((float4*)&vsh[t][0])[q] = make_float4(v4[0], v4[1], v4[2], v4[3]);
        __syncthreads();

        // u = L v : rows fb..fb+3 from register-cached Rm
        float4 a0 = ((float4*)&vsh[t][0])[0], a1 = ((float4*)&vsh[t][0])[1];
        float4 a2 = ((float4*)&vsh[t][0])[2], a3 = ((float4*)&vsh[t][0])[3];
        #pragma unroll
        for (int j = 0; j < 4; j++) {
            float4 m0 = Rm[j][0], m1 = Rm[j][1], m2 = Rm[j][2], m3 = Rm[j][3];
            u4[j] = (m0.x*a0.x + m0.y*a0.y + m0.z*a0.z + m0.w*a0.w)
                  + (m1.x*a1.x + m1.y*a1.y + m1.z*a1.z + m1.w*a1.w)
                  + (m2.x*a2.x + m2.y*a2.y + m2.z*a2.z + m2.w*a2.w)
                  + (m3.x*a3.x + m3.y*a3.y + m3.z*a3.z + m3.w*a3.w);
        }
        if (t > 0) {
            float4 vm = ((float4*)&vsh[t - 1][0])[q];
            u4[0] += elq.x * vm.x; u4[1] += elq.y * vm.y;
            u4[2] += elq.z * vm.z; u4[3] += elq.w * vm.w;
        }
        if (t < 127) {
            float4 vq = ((float4*)&vsh[t + 1][0])[q];
            u4[0] += erq.x * vq.x; u4[1] += erq.y * vq.y;
            u4[2] += erq.z * vq.z; u4[3] += erq.w * vq.w;
        }

        // publish u
        ((float4*)&ush[t][0])[q] = make_float4(u4[0], u4[1], u4[2], u4[3]);
        __syncthreads();

        // w = L^T u (transposed blocks from shared)
        float4 b0 = ((float4*)&ush[t][0])[0], b1 = ((float4*)&ush[t][0])[1];
        float4 b2 = ((float4*)&ush[t][0])[2], b3 = ((float4*)&ush[t][0])[3];
        #pragma unroll
        for (int j = 0; j < 4; j++) {
            const float4* R = (const float4*)(bnd ? &sMbT[fb + j][0] : &sMiT[fb + j][0]);
            float4 m0 = R[0], m1 = R[1], m2 = R[2], m3 = R[3];
            w4[j] = (m0.x*b0.x + m0.y*b0.y + m0.z*b0.z + m0.w*b0.w)
                  + (m1.x*b1.x + m1.y*b1.y + m1.z*b1.z + m1.w*b1.w)
                  + (m2.x*b2.x + m2.y*b2.y + m2.z*b2.z + m2.w*b2.w)
                  + (m3.x*b3.x + m3.y*b3.y + m3.z*b3.z + m3.w*b3.w);
        }
        if (t > 0) {
            float4 um = ((float4*)&ush[t - 1][0])[q];
            w4[0] += elq.x * um.x; w4[1] += elq.y * um.y;
            w4[2] += elq.z * um.z; w4[3] += elq.w * um.w;
        }
        if (t < 127) {
            float4 uq = ((float4*)&ush[t + 1][0])[q];
            w4[0] += erq.x * uq.x; w4[1] += erq.y * uq.y;
            w4[2] += erq.z * uq.z; w4[3] += erq.w * uq.w;
        }

        // fused triple reduction: alpha = v.w, r = vp.w, s = w.w
        float pa = (v4[0]*w4[0]  + v4[1]*w4[1])  + (v4[2]*w4[2]  + v4[3]*w4[3]);
        float pr = (vp4[0]*w4[0] + vp4[1]*w4[1]) + (vp4[2]*w4[2] + vp4[3]*w4[3]);
        float ps = (w4[0]*w4[0]  + w4[1]*w4[1])  + (w4[2]*w4[2]  + w4[3]*w4[3]);
        #pragma unroll
        for (int o = 16; o > 0; o >>= 1) {
            pa += __shfl_xor_sync(0xFFFFFFFFu, pa, o);
            pr += __shfl_xor_sync(0xFFFFFFFFu, pr, o);
            ps += __shfl_xor_sync(0xFFFFFFFFu, ps, o);
        }
        if (lane == 0) { sredA[wrp] = pa; sredB[wrp] = pr; sredC[wrp] = ps; }
        __syncthreads();
        float alpha = sum16(sredA);
        float rr    = sum16(sredB);
        float ss    = sum16(sredC);
        // ||w - alpha v - bprev vp||^2 (v, vp orthonormal)
        float qn = ss - alpha*alpha - 2.0f*bprev*rr + bprev*bprev;
        qn = fmaxf(qn, 0.0f);
        float beta = sqrtf(qn);
        if (tid == 0) { salpha[it] = alpha; sbeta[it] = beta; }
        float rb = (beta > 1e-30f) ? 1.0f / beta : 0.0f;
        #pragma unroll
        for (int j = 0; j < 4; j++) {
            float wn = w4[j] - alpha * v4[j] - bprev * vp4[j];
            vp4[j] = v4[j]; v4[j] = wn * rb;
        }
        bprev = beta;
    }
    __syncthreads();

    // ---- largest Ritz value of B via parallel Sturm bisection ----
    if (tid == 0) { slo = 0.0f; shi = 6.01f; }
    __syncthreads();
    for (int r = 0; r < 3; r++) {
        float lo = slo, hi = shi;
        if (tid < 128) {
            float x = lo + (hi - lo) * (float)(tid + 1) * (1.0f / 129.0f);
            int cnt = 0;
            float d = salpha[0] - x;
            if (d < 0.0f) cnt++;
            for (int i = 1; i < MLAN; i++) {
                float b = sbeta[i - 1];
                float dd = (fabsf(d) < 1e-20f) ? ((d < 0.0f) ? -1e-20f : 1e-20f) : d;
                d = (salpha[i] - x) - (b * b) / dd;
                if (d < 0.0f) cnt++;
            }
            sflag[tid] = (cnt < MLAN) ? 1 : 0;   // 1 => lambda_max >= x
        }
        __syncthreads();
        if (tid == 0) {
            float nlo = lo, nhi = hi;
            for (int i = 0; i < 128; i++) {
                float xi = lo + (hi - lo) * (float)(i + 1) * (1.0f / 129.0f);
                if (sflag[i]) nlo = xi; else { nhi = xi; break; }
            }
            slo = nlo; shi = nhi;
        }
        __syncthreads();
    }
    if (tid == 0) {
        float lmax_B = 0.5f * (slo + shi);
        g_c = 2.0f / sqrtf(lmax_B);       // 2 / sigma_max(L)
    }
}

// ---------------------------------------------------------------------------
// Kernel 2: fused main compute (R4 version: 3 barriers, no redundant compute).
// One block per batch row, thread t = time step.
// y1 = L_s^T y0, y2 = 2 L_s^T y1 - y0, out = y0 W0 + y1 W1 + y2 W2 + bias.
// ---------------------------------------------------------------------------
__global__ void __launch_bounds__(128) sgconv_main_kernel(
    const float* __restrict__ x, const float* __restrict__ weight,
    const float* __restrict__ bias, float* __restrict__ out) {
    __shared__ float sAiT[16][16], sAbT[16][16];   // (c*M - I)^T rows
    __shared__ float scei[16], sceb[16];
    __shared__ float sW0[16][16], sW1[16][16], sW2[16][16];
    __shared__ float sbias[16];
    __shared__ float vsh[128][20];

    const int tid = threadIdx.x;
    const float c = g_c;

    #pragma unroll
    for (int r = 0; r < 2; r++) {
        int i = tid + r * 128;
        int f = i >> 4, g = i & 15;
        float diag = (f == g) ? 1.0f : 0.0f;
        sAiT[g][f] = c * g_Mi[i] - diag;   // transposed store
        sAbT[g][f] = c * g_Mb[i] - diag;
        sW0[f][g] = weight[i];
        sW1[f][g] = weight[256 + i];
        sW2[f][g] = weight[512 + i];
    }
    if (tid < 16) {
        scei[tid] = c * g_eii[tid];
        sceb[tid] = c * g_ebi[tid];
        sbias[tid] = bias[tid];
    }

    const int t = tid;
    const bool bnd = (t == 0 || t == 127);

    // load x[b, t, :] (64B per thread, coalesced)
    float y0[16];
    const float4* xb = (const float4*)(x + (size_t)blockIdx.x * 2048 + t * 16);
    #pragma unroll
    for (int qq = 0; qq < 4; qq++) {
        float4 vv = xb[qq];
        y0[4*qq+0] = vv.x; y0[4*qq+1] = vv.y; y0[4*qq+2] = vv.z; y0[4*qq+3] = vv.w;
        ((float4*)&vsh[t][0])[qq] = vv;
    }
    __syncthreads();   // covers shared param init + vsh publish

    // structured apply: dst = Ls^T src + edge terms. src in regs, neighbors in vsh.
    auto apply_ls = [&](float* DST, const float* SRC) {
        float nb[16];
        #pragma unroll
        for (int f = 0; f < 16; f++) nb[f] = 0.0f;
        if (t > 0) {
            const float* el = (t == 1 || t == 127) ? sceb : scei;
            #pragma unroll
            for (int qq = 0; qq < 4; qq++) {
                float4 e4 = ((const float4*)el)[qq];
                float4 m4 = ((float4*)&vsh[t - 1][0])[qq];
                nb[4*qq+0] += e4.x * m4.x; nb[4*qq+1] += e4.y * m4.y;
                nb[4*qq+2] += e4.z * m4.z; nb[4*qq+3] += e4.w * m4.w;
            }
        }
        if (t < 127) {
            const float* er = (t == 0 || t == 126) ? sceb : scei;
            #pragma unroll
            for (int qq = 0; qq < 4; qq++) {
                float4 e4 = ((const float4*)er)[qq];
                float4 p4 = ((float4*)&vsh[t + 1][0])[qq];
                nb[4*qq+0] += e4.x * p4.x; nb[4*qq+1] += e4.y * p4.y;
                nb[4*qq+2] += e4.z * p4.z; nb[4*qq+3] += e4.w * p4.w;
            }
        }
        #pragma unroll
        for (int f = 0; f < 16; f++) {
            const float4* R = (const float4*)(bnd ? &sAbT[f][0] : &sAiT[f][0]);
            float4 m0 = R[0], m1 = R[1], m2 = R[2], m3 = R[3];
            DST[f] = nb[f]
                + (m0.x*SRC[0]  + m0.y*SRC[1]  + m0.z*SRC[2]  + m0.w*SRC[3])
                + (m1.x*SRC[4]  + m1.y*SRC[5]  + m1.z*SRC[6]  + m1.w*SRC[7])
                + (m2.x*SRC[8]  + m2.y*SRC[9]  + m2.z*SRC[10] + m2.w*SRC[11])
                + (m3.x*SRC[12] + m3.y*SRC[13] + m3.z*SRC[14] + m3.w*SRC[15]);
        }
    };

    // y1 = L_s^T y0
    float y1[16];
    apply_ls(y1, y0);
    __syncthreads();
    #pragma unroll
    for (int qq = 0; qq < 4; qq++)
        ((float4*)&vsh[t][0])[qq] = make_float4(y1[4*qq], y1[4*qq+1], y1[4*qq+2], y1[4*qq+3]);
    __syncthreads();

    // y2 = 2 * L_s^T y1 - y0
    float y2[16];
    apply_ls(y2, y1);
    #pragma unroll
    for (int f = 0; f < 16; f++) y2[f] = 2.0f * y2[f] - y0[f];

    // out[t, o] = sum_f y0 W0 + y1 W1 + y2 W2 + bias  (f-outer, o-inner)
    float ov[16];
    #pragma unroll
    for (int qq = 0; qq < 4; qq++) {
        float4 b4 = ((const float4*)sbias)[qq];
        ov[4*qq+0] = b4.x; ov[4*qq+1] = b4.y; ov[4*qq+2] = b4.z; ov[4*qq+3] = b4.w;
    }
    #pragma unroll
    for (int f = 0; f < 16; f++) {
        float a0 = y0[f], a1 = y1[f], a2 = y2[f];
        const float4* W0r = (const float4*)&sW0[f][0];
        const float4* W1r = (const float4*)&sW1[f][0];
        const float4* W2r = (const float4*)&sW2[f][0];
        #pragma unroll
        for (int qq = 0; qq < 4; qq++) {
            float4 w0 = W0r[qq], w1 = W1r[qq], w2 = W2r[qq];
            ov[4*qq+0] += a0*w0.x + a1*w1.x + a2*w2.x;
            ov[4*qq+1] += a0*w0.y + a1*w1.y + a2*w2.y;
            ov[4*qq+2] += a0*w0.z + a1*w1.z + a2*w2.z;
            ov[4*qq+3] += a0*w0.w + a1*w1.w + a2*w2.w;
        }
    }
    float4* ob = (float4*)(out + (size_t)blockIdx.x * 2048 + t * 16);
    #pragma unroll
    for (int qq = 0; qq < 4; qq++)
        ob[qq] = make_float4(ov[4*qq], ov[4*qq+1], ov[4*qq+2], ov[4*qq+3]);
}

extern "C" void kernel_launch(void* const* d_in, const int* in_sizes, int n_in,
                              void* d_out, int out_size) {
    const float* x      = (const float*)d_in[0];  // [1024,128,16]
    const float* weight = (const float*)d_in[1];  // [3,16,16]
    const float* bias   = (const float*)d_in[2];  // [16]
    const float* adj    = (const float*)d_in[3];  // [16,16]
    int batch = in_sizes[0] / (T_LEN * F_DIM);

    setup_lanczos_kernel<<<1, 512>>>(adj);
    sgconv_main_kernel<<<batch, 128>>>(x, weight, bias, (float*)d_out);
}

// round 7
// speedup vs baseline: 5.9190x; 1.4788x over previous
#include <cuda_runtime.h>
#include <math.h>

#define T_LEN 128
#define F_DIM 16

// Operator parameters (lap is block-tridiagonal; fully described by these):
__device__ float g_Mi[256];   // interior diagonal block of lap (16x16), row-major M[f][g]
__device__ float g_Mb[256];   // boundary diagonal block (t=0,127)
__device__ float g_eii[16];   // interior-interior temporal coupling (diag 16-vec)
__device__ float g_ebi[16];   // boundary-interior temporal coupling
__device__ float g_c;         // 2 / sigma_max(lap)

// ---------------------------------------------------------------------------
// Kernel 1 (analytic): sigma_max(L) via modal decomposition.
// L0 = I (x) Mi + S (x) Eii, S = path-128 adjacency = Q Lam Q^T (orthogonal)
//   => sigma(L0) = union_k sigma(Mi + lam_k Eii), lam_k = 2cos(k pi/129).
// Boundary corrections (t=0,127) perturb sigma_max by ~1e-5 (extremal temporal
// mode has sin(pi/129) boundary amplitude; no bound state since eps << J).
// Thread k (128 threads) runs an exact 16-step Lanczos on B_k = A_k^T A_k,
// A_k = Mi + lam_k Eii (16x16), then Sturm bisection; block-max -> c.
// No block barriers inside the loop; all shared reads are broadcasts.
// ---------------------------------------------------------------------------
__global__ void __launch_bounds__(128) setup_analytic_kernel(const float* __restrict__ adj) {
    __shared__ float sAhat[16][16];
    __shared__ float sMi[16][16], sMiT[16][16];
    __shared__ float seii[16];
    __shared__ float spb[16], spi[16];
    __shared__ float swmax[4];

    const int tid  = threadIdx.x;
    const int lane = tid & 31;
    const int wrp  = tid >> 5;

    // ---- build Ahat = sigmoid(adj) off-diagonal + I (row-major [f][g]) ----
    for (int i = tid; i < 256; i += 128) {
        int f = i >> 4, g = i & 15;
        sAhat[f][g] = (f == g) ? 1.0f : 1.0f / (1.0f + expf(-adj[i]));
    }
    __syncthreads();

    // ---- degrees (ROW sums): d[(t,f)] = rowsum_f + s_t ----
    if (tid < 16) {
        float a = 0.0f;
        #pragma unroll
        for (int g = 0; g < 16; g++) a += sAhat[tid][g];   // includes diag 1
        spb[tid] = rsqrtf(a + 1.0f);   // boundary (one temporal edge)
        spi[tid] = rsqrtf(a + 2.0f);   // interior (two temporal edges)
    }
    __syncthreads();

    // ---- lap blocks (also store boundary variants for the main kernel) ----
    for (int i = tid; i < 256; i += 128) {
        int f = i >> 4, g = i & 15;
        float diag = (f == g) ? 1.0f : 0.0f;
        float mi = diag - spi[f] * sAhat[f][g] * spi[g];
        float mb = diag - spb[f] * sAhat[f][g] * spb[g];
        sMi[f][g] = mi;  sMiT[g][f] = mi;
        g_Mi[i] = mi;    g_Mb[i] = mb;
    }
    if (tid < 16) {
        float eii = -spi[tid] * spi[tid];
        seii[tid] = eii;
        g_eii[tid] = eii;
        g_ebi[tid] = -spb[tid] * spi[tid];
    }
    __syncthreads();

    // ---- per-thread: 16-step Lanczos on B_k = A_k^T A_k (exact in 16 dims) ----
    const int k = tid;                      // temporal mode 0..127
    const float lam = 2.0f * cosf((float)(k + 1) * 3.14159265358979f / 129.0f);

    float v[16], vp[16];
    #pragma unroll
    for (int f = 0; f < 16; f++) {
        unsigned h = (unsigned)(k * 16 + f) * 2654435761u + 0x9E3779B9u;
        h ^= h >> 15; h *= 0x2C1B3C6Du; h ^= h >> 12; h *= 0x297A2D39u; h ^= h >> 15;
        v[f] = (float)(h & 0xFFFFFFu) * (1.0f / 16777216.0f) - 0.5f;
        vp[f] = 0.0f;
    }
    {
        float nn = 0.0f;
        #pragma unroll
        for (int f = 0; f < 16; f++) nn += v[f] * v[f];
        float r = rsqrtf(nn);
        #pragma unroll
        for (int f = 0; f < 16; f++) v[f] *= r;
    }

    float al[16], be[16];
    float bprev = 0.0f;
    for (int it = 0; it < 16; it++) {
        // a = A_k v = Mi v + lam * eii .* v
        float a[16];
        #pragma unroll
        for (int f = 0; f < 16; f++) {
            const float4* R = (const float4*)&sMi[f][0];
            float4 m0 = R[0], m1 = R[1], m2 = R[2], m3 = R[3];
            a[f] = lam * seii[f] * v[f]
                + (m0.x*v[0]  + m0.y*v[1]  + m0.z*v[2]  + m0.w*v[3])
                + (m1.x*v[4]  + m1.y*v[5]  + m1.z*v[6]  + m1.w*v[7])
                + (m2.x*v[8]  + m2.y*v[9]  + m2.z*v[10] + m2.w*v[11])
                + (m3.x*v[12] + m3.y*v[13] + m3.z*v[14] + m3.w*v[15]);
        }
        // w = A_k^T a = Mi^T a + lam * eii .* a
        float w[16];
        #pragma unroll
        for (int f = 0; f < 16; f++) {
            const float4* R = (const float4*)&sMiT[f][0];
            float4 m0 = R[0], m1 = R[1], m2 = R[2], m3 = R[3];
            w[f] = lam * seii[f] * a[f]
                + (m0.x*a[0]  + m0.y*a[1]  + m0.z*a[2]  + m0.w*a[3])
                + (m1.x*a[4]  + m1.y*a[5]  + m1.z*a[6]  + m1.w*a[7])
                + (m2.x*a[8]  + m2.y*a[9]  + m2.z*a[10] + m2.w*a[11])
                + (m3.x*a[12] + m3.y*a[13] + m3.z*a[14] + m3.w*a[15]);
        }
        float alpha = 0.0f;
        #pragma unroll
        for (int f = 0; f < 16; f++) alpha += v[f] * w[f];
        float nn = 0.0f;
        #pragma unroll
        for (int f = 0; f < 16; f++) {
            w[f] -= alpha * v[f] + bprev * vp[f];
            nn += w[f] * w[f];
        }
        float beta = sqrtf(nn);
        al[it] = alpha; be[it] = beta;
        float rb = (beta > 1e-30f) ? 1.0f / beta : 0.0f;
        #pragma unroll
        for (int f = 0; f < 16; f++) { vp[f] = v[f]; v[f] = w[f] * rb; }
        bprev = beta;
    }

    // ---- Sturm bisection: largest eigenvalue of T_k (16x16 tridiagonal) ----
    float lo = 0.0f, hi = 8.0f;
    for (int r = 0; r < 36; r++) {
        float x = 0.5f * (lo + hi);
        int cnt = 0;
        float d = al[0] - x;
        if (d < 0.0f) cnt++;
        for (int i = 1; i < 16; i++) {
            float dd = (fabsf(d) < 1e-25f) ? ((d < 0.0f) ? -1e-25f : 1e-25f) : d;
            d = (al[i] - x) - (be[i - 1] * be[i - 1]) / dd;
            if (d < 0.0f) cnt++;
        }
        if (cnt < 16) lo = x; else hi = x;   // lambda_max >= x iff cnt < 16
    }
    float lmax = 0.5f * (lo + hi);           // lambda_max(B_k) = sigma_max(A_k)^2

    // ---- block max over 128 threads ----
    #pragma unroll
    for (int o = 16; o > 0; o >>= 1)
        lmax = fmaxf(lmax, __shfl_xor_sync(0xFFFFFFFFu, lmax, o));
    if (lane == 0) swmax[wrp] = lmax;
    __syncthreads();
    if (tid == 0) {
        float m = fmaxf(fmaxf(swmax[0], swmax[1]), fmaxf(swmax[2], swmax[3]));
        g_c = 2.0f / sqrtf(m);               // 2 / sigma_max(L)
    }
}

// ---------------------------------------------------------------------------
// Kernel 2: fused main compute (unchanged, known-good 27 us).
// One block per batch row, thread t = time step.
// y1 = L_s^T y0, y2 = 2 L_s^T y1 - y0, out = y0 W0 + y1 W1 + y2 W2 + bias.
// ---------------------------------------------------------------------------
__global__ void __launch_bounds__(128) sgconv_main_kernel(
    const float* __restrict__ x, const float* __restrict__ weight,
    const float* __restrict__ bias, float* __restrict__ out) {
    __shared__ float sAiT[16][16], sAbT[16][16];   // (c*M - I)^T rows
    __shared__ float scei[16], sceb[16];
    __shared__ float sW0[16][16], sW1[16][16], sW2[16][16];
    __shared__ float sbias[16];
    __shared__ float vsh[128][20];

    const int tid = threadIdx.x;
    const float c = g_c;

    #pragma unroll
    for (int r = 0; r < 2; r++) {
        int i = tid + r * 128;
        int f = i >> 4, g = i & 15;
        float diag = (f == g) ? 1.0f : 0.0f;
        sAiT[g][f] = c * g_Mi[i] - diag;   // transposed store
        sAbT[g][f] = c * g_Mb[i] - diag;
        sW0[f][g] = weight[i];
        sW1[f][g] = weight[256 + i];
        sW2[f][g] = weight[512 + i];
    }
    if (tid < 16) {
        scei[tid] = c * g_eii[tid];
        sceb[tid] = c * g_ebi[tid];
        sbias[tid] = bias[tid];
    }

    const int t = tid;
    const bool bnd = (t == 0 || t == 127);

    // load x[b, t, :] (64B per thread, coalesced)
    float y0[16];
    const float4* xb = (const float4*)(x + (size_t)blockIdx.x * 2048 + t * 16);
    #pragma unroll
    for (int qq = 0; qq < 4; qq++) {
        float4 vv = xb[qq];
        y0[4*qq+0] = vv.x; y0[4*qq+1] = vv.y; y0[4*qq+2] = vv.z; y0[4*qq+3] = vv.w;
        ((float4*)&vsh[t][0])[qq] = vv;
    }
    __syncthreads();   // covers shared param init + vsh publish

    // structured apply: dst = Ls^T src + edge terms. src in regs, neighbors in vsh.
    auto apply_ls = [&](float* DST, const float* SRC) {
        float nb[16];
        #pragma unroll
        for (int f = 0; f < 16; f++) nb[f] = 0.0f;
        if (t > 0) {
            const float* el = (t == 1 || t == 127) ? sceb : scei;
            #pragma unroll
            for (int qq = 0; qq < 4; qq++) {
                float4 e4 = ((const float4*)el)[qq];
                float4 m4 = ((float4*)&vsh[t - 1][0])[qq];
                nb[4*qq+0] += e4.x * m4.x; nb[4*qq+1] += e4.y * m4.y;
                nb[4*qq+2] += e4.z * m4.z; nb[4*qq+3] += e4.w * m4.w;
            }
        }
        if (t < 127) {
            const float* er = (t == 0 || t == 126) ? sceb : scei;
            #pragma unroll
            for (int qq = 0; qq < 4; qq++) {
                float4 e4 = ((const float4*)er)[qq];
                float4 p4 = ((float4*)&vsh[t + 1][0])[qq];
                nb[4*qq+0] += e4.x * p4.x; nb[4*qq+1] += e4.y * p4.y;
                nb[4*qq+2] += e4.z * p4.z; nb[4*qq+3] += e4.w * p4.w;
            }
        }
        #pragma unroll
        for (int f = 0; f < 16; f++) {
            const float4* R = (const float4*)(bnd ? &sAbT[f][0] : &sAiT[f][0]);
            float4 m0 = R[0], m1 = R[1], m2 = R[2], m3 = R[3];
            DST[f] = nb[f]
                + (m0.x*SRC[0]  + m0.y*SRC[1]  + m0.z*SRC[2]  + m0.w*SRC[3])
                + (m1.x*SRC[4]  + m1.y*SRC[5]  + m1.z*SRC[6]  + m1.w*SRC[7])
                + (m2.x*SRC[8]  + m2.y*SRC[9]  + m2.z*SRC[10] + m2.w*SRC[11])
                + (m3.x*SRC[12] + m3.y*SRC[13] + m3.z*SRC[14] + m3.w*SRC[15]);
        }
    };

    // y1 = L_s^T y0
    float y1[16];
    apply_ls(y1, y0);
    __syncthreads();
    #pragma unroll
    for (int qq = 0; qq < 4; qq++)
        ((float4*)&vsh[t][0])[qq] = make_float4(y1[4*qq], y1[4*qq+1], y1[4*qq+2], y1[4*qq+3]);
    __syncthreads();

    // y2 = 2 * L_s^T y1 - y0
    float y2[16];
    apply_ls(y2, y1);
    #pragma unroll
    for (int f = 0; f < 16; f++) y2[f] = 2.0f * y2[f] - y0[f];

    // out[t, o] = sum_f y0 W0 + y1 W1 + y2 W2 + bias  (f-outer, o-inner)
    float ov[16];
    #pragma unroll
    for (int qq = 0; qq < 4; qq++) {
        float4 b4 = ((const float4*)sbias)[qq];
        ov[4*qq+0] = b4.x; ov[4*qq+1] = b4.y; ov[4*qq+2] = b4.z; ov[4*qq+3] = b4.w;
    }
    #pragma unroll
    for (int f = 0; f < 16; f++) {
        float a0 = y0[f], a1 = y1[f], a2 = y2[f];
        const float4* W0r = (const float4*)&sW0[f][0];
        const float4* W1r = (const float4*)&sW1[f][0];
        const float4* W2r = (const float4*)&sW2[f][0];
        #pragma unroll
        for (int qq = 0; qq < 4; qq++) {
            float4 w0 = W0r[qq], w1 = W1r[qq], w2 = W2r[qq];
            ov[4*qq+0] += a0*w0.x + a1*w1.x + a2*w2.x;
            ov[4*qq+1] += a0*w0.y + a1*w1.y + a2*w2.y;
            ov[4*qq+2] += a0*w0.z + a1*w1.z + a2*w2.z;
            ov[4*qq+3] += a0*w0.w + a1*w1.w + a2*w2.w;
        }
    }
    float4* ob = (float4*)(out + (size_t)blockIdx.x * 2048 + t * 16);
    #pragma unroll
    for (int qq = 0; qq < 4; qq++)
        ob[qq] = make_float4(ov[4*qq], ov[4*qq+1], ov[4*qq+2], ov[4*qq+3]);
}

extern "C" void kernel_launch(void* const* d_in, const int* in_sizes, int n_in,
                              void* d_out, int out_size) {
    const float* x      = (const float*)d_in[0];  // [1024,128,16]
    const float* weight = (const float*)d_in[1];  // [3,16,16]
    const float* bias   = (const float*)d_in[2];  // [16]
    const float* adj    = (const float*)d_in[3];  // [16,16]
    int batch = in_sizes[0] / (T_LEN * F_DIM);

    setup_analytic_kernel<<<1, 128>>>(adj);
    sgconv_main_kernel<<<batch, 128>>>(x, weight, bias, (float*)d_out);
}

// round 8
// speedup vs baseline: 15.0960x; 2.5504x over previous
#include <cuda_runtime.h>
#include <math.h>

#define T_LEN 128
#define F_DIM 16

// Operator parameters (lap is block-tridiagonal; fully described by these):
__device__ float g_Mi[256];   // interior diagonal block of lap (16x16), row-major M[f][g]
__device__ float g_Mb[256];   // boundary diagonal block (t=0,127)
__device__ float g_eii[16];   // interior-interior temporal coupling (diag 16-vec)
__device__ float g_ebi[16];   // boundary-interior temporal coupling
__device__ float g_c;         // 2 / sigma_max(lap)

// ---------------------------------------------------------------------------
// Kernel 1 (analytic, warp-parallel): sigma_max(L) via modal decomposition.
// sigma(L0) = union_k sigma(Mi + lam_k Eii), lam_k = 2cos(k pi/129).
// sigma_max(Mi + lam Eii) is CONVEX in lam (norm of affine map) => the max over
// the discrete lam_k set is attained at lam_1 = 2cos(pi/129) or lam_128 = -lam_1.
// One warp: lanes 0-15 hold the 16 components of mode +lam, lanes 16-31 of
// mode -lam. 16-step Lanczos on B = A^T A (exact in 16 dims) with scalar
// per-lane state; eigenvalue via 16-point grid Sturm bisection (6 rounds).
// ---------------------------------------------------------------------------
__global__ void __launch_bounds__(128) setup_analytic_kernel(const float* __restrict__ adj) {
    __shared__ float sAhat[16][16];
    __shared__ float sMi[16][16], sMiT[16][16];
    __shared__ float seii[16];
    __shared__ float spb[16], spi[16];

    const int tid = threadIdx.x;

    // ---- build Ahat = sigmoid(adj) off-diagonal + I (row-major [f][g]) ----
    if (tid < 256) {
        // (block has 128 threads; strided loop)
    }
    for (int i = tid; i < 256; i += 128) {
        int f = i >> 4, g = i & 15;
        sAhat[f][g] = (f == g) ? 1.0f : 1.0f / (1.0f + expf(-adj[i]));
    }
    __syncthreads();

    // ---- degrees (ROW sums): d[(t,f)] = rowsum_f + s_t ----
    if (tid < 16) {
        float a = 0.0f;
        #pragma unroll
        for (int g = 0; g < 16; g++) a += sAhat[tid][g];   // includes diag 1
        spb[tid] = rsqrtf(a + 1.0f);   // boundary (one temporal edge)
        spi[tid] = rsqrtf(a + 2.0f);   // interior (two temporal edges)
    }
    __syncthreads();

    // ---- lap blocks (store boundary variants for the main kernel too) ----
    for (int i = tid; i < 256; i += 128) {
        int f = i >> 4, g = i & 15;
        float diag = (f == g) ? 1.0f : 0.0f;
        float mi = diag - spi[f] * sAhat[f][g] * spi[g];
        float mb = diag - spb[f] * sAhat[f][g] * spb[g];
        sMi[f][g] = mi;  sMiT[g][f] = mi;
        g_Mi[i] = mi;    g_Mb[i] = mb;
    }
    if (tid < 16) {
        seii[tid] = -spi[tid] * spi[tid];
        g_eii[tid] = seii[tid];
        g_ebi[tid] = -spb[tid] * spi[tid];
    }
    __syncthreads();

    if (tid >= 32) return;   // warp 0 does the eigen solve

    const int lane = tid;            // 0..31
    const int half = lane >> 4;      // 0: +lam, 1: -lam
    const int f    = lane & 15;      // component index
    const int base = half << 4;
    const float lam = (half ? -2.0f : 2.0f) * cosf(3.14159265358979f / 129.0f);

    // register-cache row f of Mi and of Mi^T, and eii_f
    float Mr[16], Tr[16];
    #pragma unroll
    for (int g = 0; g < 16; g++) { Mr[g] = sMi[f][g]; Tr[g] = sMiT[f][g]; }
    const float le = lam * seii[f];

    // init v (per-lane scalar component), normalize within 16-lane group
    float v, vp = 0.0f;
    {
        unsigned h = (unsigned)(f * 2654435761u) + 0x9E3779B9u;
        h ^= h >> 15; h *= 0x2C1B3C6Du; h ^= h >> 12; h *= 0x297A2D39u; h ^= h >> 15;
        v = (float)(h & 0xFFFFFFu) * (1.0f / 16777216.0f) - 0.5f + 0.03f * (float)f;
        float nn = v * v;
        #pragma unroll
        for (int o = 8; o > 0; o >>= 1) nn += __shfl_xor_sync(0xFFFFFFFFu, nn, o);
        v *= rsqrtf(nn);
    }

    float al[16], be[16];
    float bprev = 0.0f;
    #pragma unroll
    for (int it = 0; it < 16; it++) {
        // a = A v : a_f = lam*e_f*v_f + sum_g Mi[f][g] v_g
        float a = le * v;
        #pragma unroll
        for (int g = 0; g < 16; g++)
            a += Mr[g] * __shfl_sync(0xFFFFFFFFu, v, base + g);
        // w = A^T a
        float w = le * a;
        #pragma unroll
        for (int g = 0; g < 16; g++)
            w += Tr[g] * __shfl_sync(0xFFFFFFFFu, a, base + g);
        // alpha = v.w (16-wide butterfly stays within the half)
        float pa = v * w;
        #pragma unroll
        for (int o = 8; o > 0; o >>= 1) pa += __shfl_xor_sync(0xFFFFFFFFu, pa, o);
        float alpha = pa;
        w -= alpha * v + bprev * vp;
        float ps = w * w;
        #pragma unroll
        for (int o = 8; o > 0; o >>= 1) ps += __shfl_xor_sync(0xFFFFFFFFu, ps, o);
        float beta = sqrtf(ps);
        al[it] = alpha; be[it] = beta;
        float rb = (beta > 1e-30f) ? 1.0f / beta : 0.0f;
        vp = v; v = w * rb;
        bprev = beta;
    }

    // ---- grid-parallel Sturm bisection: lambda_max of 16x16 tridiagonal ----
    // 16 lanes per half evaluate a 16-point grid; bracket shrinks 17x/round.
    float lo = 0.0f, hi = 8.0f;
    for (int r = 0; r < 6; r++) {
        float x = lo + (hi - lo) * (float)(f + 1) * (1.0f / 17.0f);
        int cnt = 0;
        float d = al[0] - x;
        if (d < 0.0f) cnt++;
        #pragma unroll
        for (int i = 1; i < 16; i++) {
            float dd = (fabsf(d) < 1e-25f) ? ((d < 0.0f) ? -1e-25f : 1e-25f) : d;
            d = (al[i] - x) - (be[i - 1] * be[i - 1]) / dd;
            if (d < 0.0f) cnt++;
        }
        bool ge = (cnt < 16);   // lambda_max >= x
        unsigned m = (__ballot_sync(0xFFFFFFFFu, ge) >> (half << 4)) & 0xFFFFu;
        int nge = __popc(m);    // monotone => prefix; # grid points below lmax
        float w17 = (hi - lo) * (1.0f / 17.0f);
        float nlo = lo + w17 * (float)nge;
        float nhi = lo + w17 * (float)(nge + 1);
        lo = nlo; hi = nhi;
    }
    float lmax = 0.5f * (lo + hi);   // lambda_max(B_half) = sigma_max(A_half)^2

    // combine the two halves, write c
    float other = __shfl_sync(0xFFFFFFFFu, lmax, lane ^ 16);
    lmax = fmaxf(lmax, other);
    if (lane == 0) g_c = 2.0f / sqrtf(lmax);
}

// ---------------------------------------------------------------------------
// Kernel 2: fused main compute (unchanged, known-good ~27 us).
// One block per batch row, thread t = time step.
// y1 = L_s^T y0, y2 = 2 L_s^T y1 - y0, out = y0 W0 + y1 W1 + y2 W2 + bias.
// ---------------------------------------------------------------------------
__global__ void __launch_bounds__(128) sgconv_main_kernel(
    const float* __restrict__ x, const float* __restrict__ weight,
    const float* __restrict__ bias, float* __restrict__ out) {
    __shared__ float sAiT[16][16], sAbT[16][16];   // (c*M - I)^T rows
    __shared__ float scei[16], sceb[16];
    __shared__ float sW0[16][16], sW1[16][16], sW2[16][16];
    __shared__ float sbias[16];
    __shared__ float vsh[128][20];

    const int tid = threadIdx.x;
    const float c = g_c;

    #pragma unroll
    for (int r = 0; r < 2; r++) {
        int i = tid + r * 128;
        int f = i >> 4, g = i & 15;
        float diag = (f == g) ? 1.0f : 0.0f;
        sAiT[g][f] = c * g_Mi[i] - diag;   // transposed store
        sAbT[g][f] = c * g_Mb[i] - diag;
        sW0[f][g] = weight[i];
        sW1[f][g] = weight[256 + i];
        sW2[f][g] = weight[512 + i];
    }
    if (tid < 16) {
        scei[tid] = c * g_eii[tid];
        sceb[tid] = c * g_ebi[tid];
        sbias[tid] = bias[tid];
    }

    const int t = tid;
    const bool bnd = (t == 0 || t == 127);

    // load x[b, t, :] (64B per thread, coalesced)
    float y0[16];
    const float4* xb = (const float4*)(x + (size_t)blockIdx.x * 2048 + t * 16);
    #pragma unroll
    for (int qq = 0; qq < 4; qq++) {
        float4 vv = xb[qq];
        y0[4*qq+0] = vv.x; y0[4*qq+1] = vv.y; y0[4*qq+2] = vv.z; y0[4*qq+3] = vv.w;
        ((float4*)&vsh[t][0])[qq] = vv;
    }
    __syncthreads();   // covers shared param init + vsh publish

    // structured apply: dst = Ls^T src + edge terms. src in regs, neighbors in vsh.
    auto apply_ls = [&](float* DST, const float* SRC) {
        float nb[16];
        #pragma unroll
        for (int f = 0; f < 16; f++) nb[f] = 0.0f;
        if (t > 0) {
            const float* el = (t == 1 || t == 127) ? sceb : scei;
            #pragma unroll
            for (int qq = 0; qq < 4; qq++) {
                float4 e4 = ((const float4*)el)[qq];
                float4 m4 = ((float4*)&vsh[t - 1][0])[qq];
                nb[4*qq+0] += e4.x * m4.x; nb[4*qq+1] += e4.y * m4.y;
                nb[4*qq+2] += e4.z * m4.z; nb[4*qq+3] += e4.w * m4.w;
            }
        }
        if (t < 127) {
            const float* er = (t == 0 || t == 126) ? sceb : scei;
            #pragma unroll
            for (int qq = 0; qq < 4; qq++) {
                float4 e4 = ((const float4*)er)[qq];
                float4 p4 = ((float4*)&vsh[t + 1][0])[qq];
                nb[4*qq+0] += e4.x * p4.x; nb[4*qq+1] += e4.y * p4.y;
                nb[4*qq+2] += e4.z * p4.z; nb[4*qq+3] += e4.w * p4.w;
            }
        }
        #pragma unroll
        for (int f = 0; f < 16; f++) {
            const float4* R = (const float4*)(bnd ? &sAbT[f][0] : &sAiT[f][0]);
            float4 m0 = R[0], m1 = R[1], m2 = R[2], m3 = R[3];
            DST[f] = nb[f]
                + (m0.x*SRC[0]  + m0.y*SRC[1]  + m0.z*SRC[2]  + m0.w*SRC[3])
                + (m1.x*SRC[4]  + m1.y*SRC[5]  + m1.z*SRC[6]  + m1.w*SRC[7])
                + (m2.x*SRC[8]  + m2.y*SRC[9]  + m2.z*SRC[10] + m2.w*SRC[11])
                + (m3.x*SRC[12] + m3.y*SRC[13] + m3.z*SRC[14] + m3.w*SRC[15]);
        }
    };

    // y1 = L_s^T y0
    float y1[16];
    apply_ls(y1, y0);
    __syncthreads();
    #pragma unroll
    for (int qq = 0; qq < 4; qq++)
        ((float4*)&vsh[t][0])[qq] = make_float4(y1[4*qq], y1[4*qq+1], y1[4*qq+2], y1[4*qq+3]);
    __syncthreads();

    // y2 = 2 * L_s^T y1 - y0
    float y2[16];
    apply_ls(y2, y1);
    #pragma unroll
    for (int f = 0; f < 16; f++) y2[f] = 2.0f * y2[f] - y0[f];

    // out[t, o] = sum_f y0 W0 + y1 W1 + y2 W2 + bias  (f-outer, o-inner)
    float ov[16];
    #pragma unroll
    for (int qq = 0; qq < 4; qq++) {
        float4 b4 = ((const float4*)sbias)[qq];
        ov[4*qq+0] = b4.x; ov[4*qq+1] = b4.y; ov[4*qq+2] = b4.z; ov[4*qq+3] = b4.w;
    }
    #pragma unroll
    for (int f = 0; f < 16; f++) {
        float a0 = y0[f], a1 = y1[f], a2 = y2[f];
        const float4* W0r = (const float4*)&sW0[f][0];
        const float4* W1r = (const float4*)&sW1[f][0];
        const float4* W2r = (const float4*)&sW2[f][0];
        #pragma unroll
        for (int qq = 0; qq < 4; qq++) {
            float4 w0 = W0r[qq], w1 = W1r[qq], w2 = W2r[qq];
            ov[4*qq+0] += a0*w0.x + a1*w1.x + a2*w2.x;
            ov[4*qq+1] += a0*w0.y + a1*w1.y + a2*w2.y;
            ov[4*qq+2] += a0*w0.z + a1*w1.z + a2*w2.z;
            ov[4*qq+3] += a0*w0.w + a1*w1.w + a2*w2.w;
        }
    }
    float4* ob = (float4*)(out + (size_t)blockIdx.x * 2048 + t * 16);
    #pragma unroll
    for (int qq = 0; qq < 4; qq++)
        ob[qq] = make_float4(ov[4*qq], ov[4*qq+1], ov[4*qq+2], ov[4*qq+3]);
}

extern "C" void kernel_launch(void* const* d_in, const int* in_sizes, int n_in,
                              void* d_out, int out_size) {
    const float* x      = (const float*)d_in[0];  // [1024,128,16]
    const float* weight = (const float*)d_in[1];  // [3,16,16]
    const float* bias   = (const float*)d_in[2];  // [16]
    const float* adj    = (const float*)d_in[3];  // [16,16]
    int batch = in_sizes[0] / (T_LEN * F_DIM);

    setup_analytic_kernel<<<1, 128>>>(adj);
    sgconv_main_kernel<<<batch, 128>>>(x, weight, bias, (float*)d_out);
}